// round 1
// baseline (speedup 1.0000x reference)
#include <cuda_runtime.h>
#include <math.h>

#define Bv 256
#define Tv 128
#define Dv 512
#define Hv 1024
#define FCv 1024
#define Av 32
#define BT (Bv*Tv)      // 32768
#define G3 (3*Hv)       // 3072

// ---------------- scratch (static device globals; no allocs) ----------------
__device__ float g_xln[(size_t)BT*Dv];       // 64 MB
__device__ float g_x[(size_t)BT*FCv];        // 128 MB
__device__ float g_xg[(size_t)BT*G3];        // 384 MB
__device__ float g_hseq[(size_t)BT*Hv];      // 128 MB
__device__ float g_feats[(size_t)BT*Hv];     // 128 MB
__device__ float g_h[Bv*Hv];
__device__ float g_gh[Bv*G3];
__device__ float g_Whead[2*Av*Hv];
__device__ float g_bhead[2*Av];
__device__ float g_headtmp[(size_t)BT*2*Av]; // 8 MB

// ---------------- LayerNorm over D=512 ----------------
__global__ void ln_kernel(const float* __restrict__ obs,
                          const float* __restrict__ gamma,
                          const float* __restrict__ beta) {
    int row = blockIdx.x;              // 0..BT-1
    int tid = threadIdx.x;             // 128 threads
    const float* o = obs + (size_t)row * Dv;
    float v[4];
    float s = 0.f, ss = 0.f;
#pragma unroll
    for (int i = 0; i < 4; i++) {
        v[i] = o[tid + i * 128];
        s += v[i]; ss += v[i] * v[i];
    }
    __shared__ float red0[32], red1[32];
    for (int off = 16; off; off >>= 1) {
        s  += __shfl_xor_sync(0xffffffffu, s,  off);
        ss += __shfl_xor_sync(0xffffffffu, ss, off);
    }
    int warp = tid >> 5, lane = tid & 31;
    if (lane == 0) { red0[warp] = s; red1[warp] = ss; }
    __syncthreads();
    if (warp == 0) {
        s  = (lane < 4) ? red0[lane] : 0.f;
        ss = (lane < 4) ? red1[lane] : 0.f;
        for (int off = 2; off; off >>= 1) {
            s  += __shfl_xor_sync(0xffffffffu, s,  off);
            ss += __shfl_xor_sync(0xffffffffu, ss, off);
        }
        if (lane == 0) { red0[0] = s; red1[0] = ss; }
    }
    __syncthreads();
    float mean = red0[0] * (1.0f / Dv);
    float var  = red1[0] * (1.0f / Dv) - mean * mean;
    float rstd = rsqrtf(var + 1e-5f);
    float* xo = g_xln + (size_t)row * Dv;
#pragma unroll
    for (int i = 0; i < 4; i++) {
        int c = tid + i * 128;
        xo[c] = (v[i] - mean) * rstd * gamma[c] + beta[c];
    }
}

// ---------------- Generic fp32 SGEMM: C = A(MxK) * W(NxK)^T + bias ----------
// EPI: 0 = none, 1 = relu.  MASK: multiply A rows by (1 - mask[row*maskStride])
// All of M, N divisible by 64; K divisible by 16 (true for every call here).
template<int EPI, bool MASK>
__global__ __launch_bounds__(256) void sgemm(
    int M, int N, int K,
    const float* __restrict__ Ap, int lda,
    const float* __restrict__ Wp,           // N x K row-major
    const float* __restrict__ bias,
    float* __restrict__ Cp, int ldc,
    const int* __restrict__ mask, int maskStride)
{
    __shared__ float As[16][64];
    __shared__ float Bs[16][65];

    int bm = blockIdx.y, bn = blockIdx.x;
    int tid = threadIdx.x;
    int tx = tid & 15, ty = tid >> 4;

    const float* Ab = Ap + (size_t)(bm * 64) * lda;
    const float* Wb = Wp + (size_t)(bn * 64) * K;

    float acc[4][4];
#pragma unroll
    for (int i = 0; i < 4; i++)
#pragma unroll
        for (int j = 0; j < 4; j++) acc[i][j] = 0.f;

    for (int k0 = 0; k0 < K; k0 += 16) {
#pragma unroll
        for (int i = 0; i < 4; i++) {
            int e = tid + i * 256;         // 0..1023
            int r = e >> 4, c = e & 15;
            float a = Ab[(size_t)r * lda + k0 + c];
            if (MASK) a *= (1.0f - (float)mask[(size_t)(bm * 64 + r) * maskStride]);
            As[c][r] = a;
        }
#pragma unroll
        for (int i = 0; i < 4; i++) {
            int e = tid + i * 256;
            int n = e >> 4, c = e & 15;
            Bs[c][n] = Wb[(size_t)n * K + k0 + c];
        }
        __syncthreads();
#pragma unroll
        for (int k = 0; k < 16; k++) {
            float a[4], b[4];
#pragma unroll
            for (int i = 0; i < 4; i++) a[i] = As[k][ty * 4 + i];
#pragma unroll
            for (int j = 0; j < 4; j++) b[j] = Bs[k][tx * 4 + j];
#pragma unroll
            for (int i = 0; i < 4; i++)
#pragma unroll
                for (int j = 0; j < 4; j++)
                    acc[i][j] = fmaf(a[i], b[j], acc[i][j]);
        }
        __syncthreads();
    }

#pragma unroll
    for (int i = 0; i < 4; i++) {
        int r = bm * 64 + ty * 4 + i;
#pragma unroll
        for (int j = 0; j < 4; j++) {
            int n = bn * 64 + tx * 4 + j;
            float v = acc[i][j] + bias[n];
            if (EPI == 1) v = fmaxf(v, 0.0f);
            Cp[(size_t)r * ldc + n] = v;
        }
    }
}

// ---------------- GRU gates (elementwise, per step) ----------------
__global__ void gru_gates(int t, const int* __restrict__ starts) {
    int idx = blockIdx.x * blockDim.x + threadIdx.x;   // 0..B*H-1
    if (idx >= Bv * Hv) return;
    int b = idx >> 10, j = idx & 1023;
    size_t xrow = ((size_t)b * Tv + t) * G3;
    float xr = g_xg[xrow + j];
    float xz = g_xg[xrow + Hv + j];
    float xn = g_xg[xrow + 2 * Hv + j];
    size_t grow = (size_t)b * G3;
    float hr = g_gh[grow + j];
    float hz = g_gh[grow + Hv + j];
    float hn = g_gh[grow + 2 * Hv + j];
    float st = (float)starts[b * Tv + t];
    float hm = g_h[idx] * (1.0f - st);
    float r = 1.0f / (1.0f + expf(-(xr + hr)));
    float z = 1.0f / (1.0f + expf(-(xz + hz)));
    float n = tanhf(xn + r * hn);
    float hnew = (1.0f - z) * n + z * hm;
    g_h[idx] = hnew;
    g_hseq[((size_t)b * Tv + t) * Hv + j] = hnew;
}

// ---------------- head weight concat ----------------
__global__ void head_prep(const float* __restrict__ Wm, const float* __restrict__ Wl,
                          const float* __restrict__ bm, const float* __restrict__ bl) {
    int i = blockIdx.x * blockDim.x + threadIdx.x;
    if (i < Av * Hv) {
        g_Whead[i] = Wm[i];
        g_Whead[Av * Hv + i] = Wl[i];
    }
    if (i < Av) { g_bhead[i] = bm[i]; g_bhead[Av + i] = bl[i]; }
}

// ---------------- head split + clip ----------------
__global__ void head_split(float* __restrict__ out) {
    int idx = blockIdx.x * blockDim.x + threadIdx.x;   // BT*64
    if (idx >= BT * 64) return;
    int row = idx >> 6, n = idx & 63;
    float v = g_headtmp[idx];
    if (n < Av) {
        out[(size_t)row * Av + n] = v;                       // means
    } else {
        v = fminf(fmaxf(v, -20.0f), 2.0f);
        out[(size_t)BT * Av + (size_t)row * Av + (n - Av)] = v;  // log_std
    }
}

// ---------------- copy initial h / final h ----------------
__global__ void copy_vec(const float* __restrict__ src, float* __restrict__ dst, int n) {
    int i = blockIdx.x * blockDim.x + threadIdx.x;
    if (i < n) dst[i] = src[i];
}
__global__ void init_h(const float* __restrict__ h0) {
    int i = blockIdx.x * blockDim.x + threadIdx.x;
    if (i < Bv * Hv) g_h[i] = h0[i];
}
__global__ void emit_h(float* __restrict__ out) {
    int i = blockIdx.x * blockDim.x + threadIdx.x;
    if (i < Bv * Hv) out[i] = g_h[i];
}

extern "C" void kernel_launch(void* const* d_in, const int* in_sizes, int n_in,
                              void* d_out, int out_size) {
    const float* obs    = (const float*)d_in[0];
    const float* h0     = (const float*)d_in[1];
    const int*   starts = (const int*)  d_in[2];
    const float* gamma  = (const float*)d_in[3];
    const float* beta   = (const float*)d_in[4];
    const float* W_fc   = (const float*)d_in[5];
    const float* b_fc   = (const float*)d_in[6];
    const float* W_ih   = (const float*)d_in[7];
    const float* b_ih   = (const float*)d_in[8];
    const float* W_hh   = (const float*)d_in[9];
    const float* b_hh   = (const float*)d_in[10];
    const float* W_out  = (const float*)d_in[11];
    const float* b_out  = (const float*)d_in[12];
    const float* W_mean = (const float*)d_in[13];
    const float* b_mean = (const float*)d_in[14];
    const float* W_ls   = (const float*)d_in[15];
    const float* b_ls   = (const float*)d_in[16];
    float* out = (float*)d_out;

    float *xln, *x, *xg, *hseq, *feats, *h, *gh, *Whead, *bhead, *headtmp;
    cudaGetSymbolAddress((void**)&xln,     g_xln);
    cudaGetSymbolAddress((void**)&x,       g_x);
    cudaGetSymbolAddress((void**)&xg,      g_xg);
    cudaGetSymbolAddress((void**)&hseq,    g_hseq);
    cudaGetSymbolAddress((void**)&feats,   g_feats);
    cudaGetSymbolAddress((void**)&h,       g_h);
    cudaGetSymbolAddress((void**)&gh,      g_gh);
    cudaGetSymbolAddress((void**)&Whead,   g_Whead);
    cudaGetSymbolAddress((void**)&bhead,   g_bhead);
    cudaGetSymbolAddress((void**)&headtmp, g_headtmp);

    // 1. LayerNorm
    ln_kernel<<<BT, 128>>>(obs, gamma, beta);

    // 2. FC: x = relu(xln @ W_fc^T + b_fc)   (32768 x 512 -> 1024)
    sgemm<1, false><<<dim3(FCv / 64, BT / 64), 256>>>(
        BT, FCv, Dv, xln, Dv, W_fc, b_fc, x, FCv, nullptr, 0);

    // 3. xg = x @ W_ih^T + b_ih   (32768 x 1024 -> 3072)
    sgemm<0, false><<<dim3(G3 / 64, BT / 64), 256>>>(
        BT, G3, FCv, x, FCv, W_ih, b_ih, xg, G3, nullptr, 0);

    // 4. init h, GRU scan (sequential in t)
    init_h<<<(Bv * Hv + 255) / 256, 256>>>(h0);
    for (int t = 0; t < Tv; t++) {
        // gh = (h * (1-st)) @ W_hh^T + b_hh   (256 x 1024 -> 3072), mask fused
        sgemm<0, true><<<dim3(G3 / 64, Bv / 64), 256>>>(
            Bv, G3, Hv, h, Hv, W_hh, b_hh, gh, G3, starts + t, Tv);
        gru_gates<<<(Bv * Hv + 255) / 256, 256>>>(t, starts);
    }

    // 5. feats = relu(hseq @ W_out^T + b_out), batched over all t
    sgemm<1, false><<<dim3(Hv / 64, BT / 64), 256>>>(
        BT, Hv, Hv, hseq, Hv, W_out, b_out, feats, Hv, nullptr, 0);

    // 6. heads: concat weights, one N=64 GEMM, then split+clip
    head_prep<<<(Av * Hv + 255) / 256, 256>>>(W_mean, W_ls, b_mean, b_ls);
    sgemm<0, false><<<dim3(1, BT / 64), 256>>>(
        BT, 64, Hv, feats, Hv, Whead, bhead, headtmp, 64, nullptr, 0);
    head_split<<<(BT * 64 + 255) / 256, 256>>>(out);

    // 7. h_final
    emit_h<<<(Bv * Hv + 255) / 256, 256>>>(out + 2 * (size_t)BT * Av);
}

// round 2
// speedup vs baseline: 1.6489x; 1.6489x over previous
#include <cuda_runtime.h>
#include <math.h>

#define Bv 256
#define Tv 128
#define Dv 512
#define Hv 1024
#define FCv 1024
#define Av 32
#define BT (Bv*Tv)      // 32768
#define G3 (3*Hv)       // 3072

// ---------------- scratch (static device globals; no allocs) ----------------
__device__ float g_xln[(size_t)BT*Dv];       // 64 MB
__device__ float g_x[(size_t)BT*FCv];        // 128 MB
__device__ float g_xg[(size_t)BT*G3];        // 384 MB
__device__ float g_hseq[(size_t)BT*Hv];      // 128 MB
__device__ float g_feats[(size_t)BT*Hv];     // 128 MB
__device__ float g_h[Bv*Hv];
__device__ float g_gh[Bv*G3];
__device__ float g_Whead[2*Av*Hv];
__device__ float g_bhead[2*Av];
__device__ float g_headtmp[(size_t)BT*2*Av]; // 8 MB

// ---------------- packed f32x2 helpers (Blackwell FFMA2) ----------------
typedef unsigned long long ull;
__device__ __forceinline__ ull pack2(float x, float y) {
    ull r; asm("mov.b64 %0, {%1, %2};" : "=l"(r) : "f"(x), "f"(y)); return r;
}
__device__ __forceinline__ void fma2(ull& d, ull a, ull b) {
    asm("fma.rn.f32x2 %0, %1, %2, %0;" : "+l"(d) : "l"(a), "l"(b));
}
__device__ __forceinline__ float2 unpack2(ull v) {
    float2 f; asm("mov.b64 {%0, %1}, %2;" : "=f"(f.x), "=f"(f.y) : "l"(v)); return f;
}

// ---------------- LayerNorm over D=512 ----------------
__global__ void ln_kernel(const float* __restrict__ obs,
                          const float* __restrict__ gamma,
                          const float* __restrict__ beta) {
    int row = blockIdx.x;              // 0..BT-1
    int tid = threadIdx.x;             // 128 threads
    const float* o = obs + (size_t)row * Dv;
    float v[4];
    float s = 0.f, ss = 0.f;
#pragma unroll
    for (int i = 0; i < 4; i++) {
        v[i] = o[tid + i * 128];
        s += v[i]; ss += v[i] * v[i];
    }
    __shared__ float red0[32], red1[32];
    for (int off = 16; off; off >>= 1) {
        s  += __shfl_xor_sync(0xffffffffu, s,  off);
        ss += __shfl_xor_sync(0xffffffffu, ss, off);
    }
    int warp = tid >> 5, lane = tid & 31;
    if (lane == 0) { red0[warp] = s; red1[warp] = ss; }
    __syncthreads();
    if (warp == 0) {
        s  = (lane < 4) ? red0[lane] : 0.f;
        ss = (lane < 4) ? red1[lane] : 0.f;
        for (int off = 2; off; off >>= 1) {
            s  += __shfl_xor_sync(0xffffffffu, s,  off);
            ss += __shfl_xor_sync(0xffffffffu, ss, off);
        }
        if (lane == 0) { red0[0] = s; red1[0] = ss; }
    }
    __syncthreads();
    float mean = red0[0] * (1.0f / Dv);
    float var  = red1[0] * (1.0f / Dv) - mean * mean;
    float rstd = rsqrtf(var + 1e-5f);
    float* xo = g_xln + (size_t)row * Dv;
#pragma unroll
    for (int i = 0; i < 4; i++) {
        int c = tid + i * 128;
        xo[c] = (v[i] - mean) * rstd * gamma[c] + beta[c];
    }
}

// ---------------- Fast fp32 SGEMM with packed f32x2 FMAs ----------------
// C = A(MxK) * W(NxK)^T + bias.  BN=128, BK=8, 256 threads.
// BM=128 -> TM=8 (8x8 per thread), BM=64 -> TM=4.
// EPI: 0 none, 1 relu. MASK: A row scaled by (1 - mask[row*maskStride]).
// Requires: M%BM==0, N%128==0, K%8==0.
template<int BM, int TM, int EPI, bool MASK>
__global__ __launch_bounds__(256) void sgemm_fast(
    int M, int N, int K,
    const float* __restrict__ Ap, int lda,
    const float* __restrict__ Wp,           // N x K row-major
    const float* __restrict__ bias,
    float* __restrict__ Cp, int ldc,
    const int* __restrict__ mask, int maskStride)
{
    constexpr int BN = 128;
    constexpr int BK = 8;
    constexpr int NP = TM / 2;   // row-pairs per thread

    __shared__ float As[2][BK][BM];
    __shared__ float Bs[2][BK][BN];

    const int tid = threadIdx.x;
    const int tx = tid & 15;        // col group: 8 cols
    const int ty = tid >> 4;        // row group: TM rows
    const int bm0 = blockIdx.y * BM;
    const int bn0 = blockIdx.x * BN;

    const float* Ab = Ap + (size_t)bm0 * lda;
    const float* Wb = Wp + (size_t)bn0 * K;

    // loader coordinates
    int arow, akq;
    if (BM == 128) { arow = tid >> 1; akq = (tid & 1) * 4; }   // float4
    else           { arow = tid >> 2; akq = (tid & 3) * 2; }   // float2
    const int brow = tid >> 1, bkq = (tid & 1) * 4;            // float4

    float amask = 1.0f;
    if (MASK) amask = 1.0f - (float)__ldg(&mask[(size_t)(bm0 + arow) * maskStride]);

    ull acc[NP][8];
#pragma unroll
    for (int p = 0; p < NP; p++)
#pragma unroll
        for (int n = 0; n < 8; n++) acc[p][n] = 0ull;

    float a_reg[4];
    float4 b_reg;

    const int nk = K / BK;

    // ---- prologue: tile 0 ----
    {
        if (BM == 128) {
            float4 v = *(const float4*)&Ab[(size_t)arow * lda + akq];
            a_reg[0] = v.x; a_reg[1] = v.y; a_reg[2] = v.z; a_reg[3] = v.w;
        } else {
            float2 v = *(const float2*)&Ab[(size_t)arow * lda + akq];
            a_reg[0] = v.x; a_reg[1] = v.y;
        }
        b_reg = *(const float4*)&Wb[(size_t)brow * K + bkq];
        if (BM == 128) {
#pragma unroll
            for (int i = 0; i < 4; i++) As[0][akq + i][arow] = a_reg[i] * amask;
        } else {
#pragma unroll
            for (int i = 0; i < 2; i++) As[0][akq + i][arow] = a_reg[i] * amask;
        }
        Bs[0][bkq + 0][brow] = b_reg.x;
        Bs[0][bkq + 1][brow] = b_reg.y;
        Bs[0][bkq + 2][brow] = b_reg.z;
        Bs[0][bkq + 3][brow] = b_reg.w;
    }
    __syncthreads();

    int buf = 0;
    for (int it = 0; it < nk; it++) {
        const bool more = (it + 1 < nk);
        if (more) {
            const int k0 = (it + 1) * BK;
            if (BM == 128) {
                float4 v = *(const float4*)&Ab[(size_t)arow * lda + k0 + akq];
                a_reg[0] = v.x; a_reg[1] = v.y; a_reg[2] = v.z; a_reg[3] = v.w;
            } else {
                float2 v = *(const float2*)&Ab[(size_t)arow * lda + k0 + akq];
                a_reg[0] = v.x; a_reg[1] = v.y;
            }
            b_reg = *(const float4*)&Wb[(size_t)brow * K + k0 + bkq];
        }

#pragma unroll
        for (int k = 0; k < BK; k++) {
            ull ap[NP];
            if (BM == 128) {
                float4 a0 = *(const float4*)&As[buf][k][ty * TM];
                float4 a1 = *(const float4*)&As[buf][k][ty * TM + 4];
                ap[0] = pack2(a0.x, a0.y); ap[1] = pack2(a0.z, a0.w);
                if (NP > 2) { ap[2] = pack2(a1.x, a1.y); ap[3] = pack2(a1.z, a1.w); }
            } else {
                float4 a0 = *(const float4*)&As[buf][k][ty * TM];
                ap[0] = pack2(a0.x, a0.y); ap[1] = pack2(a0.z, a0.w);
            }
            float4 b0 = *(const float4*)&Bs[buf][k][tx * 8];
            float4 b1 = *(const float4*)&Bs[buf][k][tx * 8 + 4];
            float bv[8] = {b0.x, b0.y, b0.z, b0.w, b1.x, b1.y, b1.z, b1.w};
#pragma unroll
            for (int n = 0; n < 8; n++) {
                ull bp = pack2(bv[n], bv[n]);
#pragma unroll
                for (int p = 0; p < NP; p++) fma2(acc[p][n], ap[p], bp);
            }
        }

        if (more) {
            if (BM == 128) {
#pragma unroll
                for (int i = 0; i < 4; i++) As[buf ^ 1][akq + i][arow] = a_reg[i] * amask;
            } else {
#pragma unroll
                for (int i = 0; i < 2; i++) As[buf ^ 1][akq + i][arow] = a_reg[i] * amask;
            }
            Bs[buf ^ 1][bkq + 0][brow] = b_reg.x;
            Bs[buf ^ 1][bkq + 1][brow] = b_reg.y;
            Bs[buf ^ 1][bkq + 2][brow] = b_reg.z;
            Bs[buf ^ 1][bkq + 3][brow] = b_reg.w;
            __syncthreads();
            buf ^= 1;
        }
    }

    // ---- epilogue ----
    float bvals[8];
#pragma unroll
    for (int n = 0; n < 8; n++) bvals[n] = bias[bn0 + tx * 8 + n];

#pragma unroll
    for (int p = 0; p < NP; p++) {
        float2 cv[8];
#pragma unroll
        for (int n = 0; n < 8; n++) cv[n] = unpack2(acc[p][n]);
        const int r0 = bm0 + ty * TM + 2 * p;
#pragma unroll
        for (int rr = 0; rr < 2; rr++) {
            float o[8];
#pragma unroll
            for (int n = 0; n < 8; n++) {
                float v = (rr == 0 ? cv[n].x : cv[n].y) + bvals[n];
                if (EPI == 1) v = fmaxf(v, 0.0f);
                o[n] = v;
            }
            float* cp = Cp + (size_t)(r0 + rr) * ldc + bn0 + tx * 8;
            *(float4*)cp       = make_float4(o[0], o[1], o[2], o[3]);
            *(float4*)(cp + 4) = make_float4(o[4], o[5], o[6], o[7]);
        }
    }
}

// ---------------- small-N SGEMM (64x64 tile) for the heads ----------------
template<int EPI, bool MASK>
__global__ __launch_bounds__(256) void sgemm(
    int M, int N, int K,
    const float* __restrict__ Ap, int lda,
    const float* __restrict__ Wp,
    const float* __restrict__ bias,
    float* __restrict__ Cp, int ldc,
    const int* __restrict__ mask, int maskStride)
{
    __shared__ float As[16][64];
    __shared__ float Bs[16][65];

    int bm = blockIdx.y, bn = blockIdx.x;
    int tid = threadIdx.x;
    int tx = tid & 15, ty = tid >> 4;

    const float* Ab = Ap + (size_t)(bm * 64) * lda;
    const float* Wb = Wp + (size_t)(bn * 64) * K;

    float acc[4][4];
#pragma unroll
    for (int i = 0; i < 4; i++)
#pragma unroll
        for (int j = 0; j < 4; j++) acc[i][j] = 0.f;

    for (int k0 = 0; k0 < K; k0 += 16) {
#pragma unroll
        for (int i = 0; i < 4; i++) {
            int e = tid + i * 256;
            int r = e >> 4, c = e & 15;
            float a = Ab[(size_t)r * lda + k0 + c];
            if (MASK) a *= (1.0f - (float)mask[(size_t)(bm * 64 + r) * maskStride]);
            As[c][r] = a;
        }
#pragma unroll
        for (int i = 0; i < 4; i++) {
            int e = tid + i * 256;
            int n = e >> 4, c = e & 15;
            Bs[c][n] = Wb[(size_t)n * K + k0 + c];
        }
        __syncthreads();
#pragma unroll
        for (int k = 0; k < 16; k++) {
            float a[4], b[4];
#pragma unroll
            for (int i = 0; i < 4; i++) a[i] = As[k][ty * 4 + i];
#pragma unroll
            for (int j = 0; j < 4; j++) b[j] = Bs[k][tx * 4 + j];
#pragma unroll
            for (int i = 0; i < 4; i++)
#pragma unroll
                for (int j = 0; j < 4; j++)
                    acc[i][j] = fmaf(a[i], b[j], acc[i][j]);
        }
        __syncthreads();
    }

#pragma unroll
    for (int i = 0; i < 4; i++) {
        int r = bm * 64 + ty * 4 + i;
#pragma unroll
        for (int j = 0; j < 4; j++) {
            int n = bn * 64 + tx * 4 + j;
            float v = acc[i][j] + bias[n];
            if (EPI == 1) v = fmaxf(v, 0.0f);
            Cp[(size_t)r * ldc + n] = v;
        }
    }
}

// ---------------- GRU gates (elementwise, per step) ----------------
__global__ void gru_gates(int t, const int* __restrict__ starts) {
    int idx = blockIdx.x * blockDim.x + threadIdx.x;   // 0..B*H-1
    if (idx >= Bv * Hv) return;
    int b = idx >> 10, j = idx & 1023;
    size_t xrow = ((size_t)b * Tv + t) * G3;
    float xr = g_xg[xrow + j];
    float xz = g_xg[xrow + Hv + j];
    float xn = g_xg[xrow + 2 * Hv + j];
    size_t grow = (size_t)b * G3;
    float hr = g_gh[grow + j];
    float hz = g_gh[grow + Hv + j];
    float hn = g_gh[grow + 2 * Hv + j];
    float st = (float)starts[b * Tv + t];
    float hm = g_h[idx] * (1.0f - st);
    float r = 1.0f / (1.0f + expf(-(xr + hr)));
    float z = 1.0f / (1.0f + expf(-(xz + hz)));
    float n = tanhf(xn + r * hn);
    float hnew = (1.0f - z) * n + z * hm;
    g_h[idx] = hnew;
    g_hseq[((size_t)b * Tv + t) * Hv + j] = hnew;
}

// ---------------- head weight concat ----------------
__global__ void head_prep(const float* __restrict__ Wm, const float* __restrict__ Wl,
                          const float* __restrict__ bm, const float* __restrict__ bl) {
    int i = blockIdx.x * blockDim.x + threadIdx.x;
    if (i < Av * Hv) {
        g_Whead[i] = Wm[i];
        g_Whead[Av * Hv + i] = Wl[i];
    }
    if (i < Av) { g_bhead[i] = bm[i]; g_bhead[Av + i] = bl[i]; }
}

// ---------------- head split + clip ----------------
__global__ void head_split(float* __restrict__ out) {
    int idx = blockIdx.x * blockDim.x + threadIdx.x;   // BT*64
    if (idx >= BT * 64) return;
    int row = idx >> 6, n = idx & 63;
    float v = g_headtmp[idx];
    if (n < Av) {
        out[(size_t)row * Av + n] = v;
    } else {
        v = fminf(fmaxf(v, -20.0f), 2.0f);
        out[(size_t)BT * Av + (size_t)row * Av + (n - Av)] = v;
    }
}

__global__ void init_h(const float* __restrict__ h0) {
    int i = blockIdx.x * blockDim.x + threadIdx.x;
    if (i < Bv * Hv) g_h[i] = h0[i];
}
__global__ void emit_h(float* __restrict__ out) {
    int i = blockIdx.x * blockDim.x + threadIdx.x;
    if (i < Bv * Hv) out[i] = g_h[i];
}

extern "C" void kernel_launch(void* const* d_in, const int* in_sizes, int n_in,
                              void* d_out, int out_size) {
    const float* obs    = (const float*)d_in[0];
    const float* h0     = (const float*)d_in[1];
    const int*   starts = (const int*)  d_in[2];
    const float* gamma  = (const float*)d_in[3];
    const float* beta   = (const float*)d_in[4];
    const float* W_fc   = (const float*)d_in[5];
    const float* b_fc   = (const float*)d_in[6];
    const float* W_ih   = (const float*)d_in[7];
    const float* b_ih   = (const float*)d_in[8];
    const float* W_hh   = (const float*)d_in[9];
    const float* b_hh   = (const float*)d_in[10];
    const float* W_out  = (const float*)d_in[11];
    const float* b_out  = (const float*)d_in[12];
    const float* W_mean = (const float*)d_in[13];
    const float* b_mean = (const float*)d_in[14];
    const float* W_ls   = (const float*)d_in[15];
    const float* b_ls   = (const float*)d_in[16];
    float* out = (float*)d_out;

    float *xln, *x, *xg, *hseq, *feats, *h, *gh, *Whead, *bhead, *headtmp;
    cudaGetSymbolAddress((void**)&xln,     g_xln);
    cudaGetSymbolAddress((void**)&x,       g_x);
    cudaGetSymbolAddress((void**)&xg,      g_xg);
    cudaGetSymbolAddress((void**)&hseq,    g_hseq);
    cudaGetSymbolAddress((void**)&feats,   g_feats);
    cudaGetSymbolAddress((void**)&h,       g_h);
    cudaGetSymbolAddress((void**)&gh,      g_gh);
    cudaGetSymbolAddress((void**)&Whead,   g_Whead);
    cudaGetSymbolAddress((void**)&bhead,   g_bhead);
    cudaGetSymbolAddress((void**)&headtmp, g_headtmp);

    // 1. LayerNorm
    ln_kernel<<<BT, 128>>>(obs, gamma, beta);

    // 2. FC: x = relu(xln @ W_fc^T + b_fc)   (32768 x 512 -> 1024)
    sgemm_fast<128, 8, 1, false><<<dim3(FCv / 128, BT / 128), 256>>>(
        BT, FCv, Dv, xln, Dv, W_fc, b_fc, x, FCv, nullptr, 0);

    // 3. xg = x @ W_ih^T + b_ih   (32768 x 1024 -> 3072)
    sgemm_fast<128, 8, 0, false><<<dim3(G3 / 128, BT / 128), 256>>>(
        BT, G3, FCv, x, FCv, W_ih, b_ih, xg, G3, nullptr, 0);

    // 4. init h, GRU scan (sequential in t)
    init_h<<<(Bv * Hv + 255) / 256, 256>>>(h0);
    for (int t = 0; t < Tv; t++) {
        // gh = (h * (1-st)) @ W_hh^T + b_hh   (256 x 1024 -> 3072), mask fused
        sgemm_fast<64, 4, 0, true><<<dim3(G3 / 128, Bv / 64), 256>>>(
            Bv, G3, Hv, h, Hv, W_hh, b_hh, gh, G3, starts + t, Tv);
        gru_gates<<<(Bv * Hv + 255) / 256, 256>>>(t, starts);
    }

    // 5. feats = relu(hseq @ W_out^T + b_out), batched over all t
    sgemm_fast<128, 8, 1, false><<<dim3(Hv / 128, BT / 128), 256>>>(
        BT, Hv, Hv, hseq, Hv, W_out, b_out, feats, Hv, nullptr, 0);

    // 6. heads: concat weights, one N=64 GEMM, then split+clip
    head_prep<<<(Av * Hv + 255) / 256, 256>>>(W_mean, W_ls, b_mean, b_ls);
    sgemm<0, false><<<dim3(1, BT / 64), 256>>>(
        BT, 64, Hv, feats, Hv, Whead, bhead, headtmp, 64, nullptr, 0);
    head_split<<<(BT * 64 + 255) / 256, 256>>>(out);

    // 7. h_final
    emit_h<<<(Bv * Hv + 255) / 256, 256>>>(out + 2 * (size_t)BT * Av);
}

// round 4
// speedup vs baseline: 5.2650x; 3.1931x over previous
#include <cuda_runtime.h>
#include <cuda_bf16.h>
#include <cstdint>
#include <math.h>

#define Bv 256
#define Tv 128
#define Dv 512
#define Hv 1024
#define FCv 1024
#define Av 32
#define BT (Bv*Tv)      // 32768
#define G3 (3*Hv)       // 3072
#define NHEAD 128       // padded head output cols
#define SKv 4           // split-K for the step GEMM

// ---------------- scratch (static device globals; no allocs) ----------------
__device__ __nv_bfloat16 g_xlnhi[(size_t)BT*Dv],  g_xlnlo[(size_t)BT*Dv];
__device__ __nv_bfloat16 g_xhi[(size_t)BT*FCv],   g_xlo[(size_t)BT*FCv];
__device__ float         g_xg[(size_t)BT*G3];
__device__ __nv_bfloat16 g_hseqhi[(size_t)BT*Hv], g_hseqlo[(size_t)BT*Hv];
__device__ __nv_bfloat16 g_featshi[(size_t)BT*Hv],g_featslo[(size_t)BT*Hv];
__device__ float         g_h[Bv*Hv];
__device__ float         g_ghp[(size_t)SKv*Bv*G3];   // split-K partials
__device__ __nv_bfloat16 g_hmhi[Bv*Hv], g_hmlo[Bv*Hv];
__device__ float         g_headtmp[(size_t)BT*NHEAD];
// split weights
__device__ __nv_bfloat16 g_wfchi[FCv*Dv],  g_wfclo[FCv*Dv];
__device__ __nv_bfloat16 g_wihhi[G3*FCv],  g_wihlo[G3*FCv];
__device__ __nv_bfloat16 g_whhhi[G3*Hv],   g_whhlo[G3*Hv];
__device__ __nv_bfloat16 g_wouthi[Hv*Hv],  g_woutlo[Hv*Hv];
__device__ __nv_bfloat16 g_wheadhi[NHEAD*Hv], g_wheadlo[NHEAD*Hv];
__device__ float         g_bheadp[NHEAD];

// ---------------- helpers ----------------
__device__ __forceinline__ uint32_t smem_u32(const void* p) {
    uint32_t a;
    asm("{ .reg .u64 t; cvta.to.shared.u64 t, %1; cvt.u32.u64 %0, t; }" : "=r"(a) : "l"(p));
    return a;
}
#define CP_ASYNC16(s, g) \
    asm volatile("cp.async.cg.shared.global [%0], [%1], 16;" :: "r"(s), "l"(g) : "memory")
#define CP_COMMIT() asm volatile("cp.async.commit_group;" ::: "memory")
#define CP_WAIT2()  asm volatile("cp.async.wait_group 2;" ::: "memory")

__device__ __forceinline__ void ldsm4(uint32_t* r, uint32_t addr) {
    asm volatile("ldmatrix.sync.aligned.m8n8.x4.shared.b16 {%0,%1,%2,%3}, [%4];"
        : "=r"(r[0]), "=r"(r[1]), "=r"(r[2]), "=r"(r[3]) : "r"(addr));
}
__device__ __forceinline__ void mma_bf16(float* d, const uint32_t* a, const uint32_t* b) {
    asm volatile("mma.sync.aligned.m16n8k16.row.col.f32.bf16.bf16.f32 "
        "{%0,%1,%2,%3}, {%4,%5,%6,%7}, {%8,%9}, {%0,%1,%2,%3};"
        : "+f"(d[0]), "+f"(d[1]), "+f"(d[2]), "+f"(d[3])
        : "r"(a[0]), "r"(a[1]), "r"(a[2]), "r"(a[3]), "r"(b[0]), "r"(b[1]));
}
__device__ __forceinline__ void bsplit(float v, __nv_bfloat16& hi, __nv_bfloat16& lo) {
    hi = __float2bfloat16(v);
    lo = __float2bfloat16(v - __bfloat162float(hi));
}

// ---------------- LayerNorm over D=512, emits bf16 split ----------------
__global__ void ln_kernel(const float* __restrict__ obs,
                          const float* __restrict__ gamma,
                          const float* __restrict__ beta) {
    int row = blockIdx.x;
    int tid = threadIdx.x;             // 128 threads
    const float* o = obs + (size_t)row * Dv;
    float v[4];
    float s = 0.f, ss = 0.f;
#pragma unroll
    for (int i = 0; i < 4; i++) {
        v[i] = o[tid + i * 128];
        s += v[i]; ss += v[i] * v[i];
    }
    __shared__ float red0[32], red1[32];
    for (int off = 16; off; off >>= 1) {
        s  += __shfl_xor_sync(0xffffffffu, s,  off);
        ss += __shfl_xor_sync(0xffffffffu, ss, off);
    }
    int warp = tid >> 5, lane = tid & 31;
    if (lane == 0) { red0[warp] = s; red1[warp] = ss; }
    __syncthreads();
    if (warp == 0) {
        s  = (lane < 4) ? red0[lane] : 0.f;
        ss = (lane < 4) ? red1[lane] : 0.f;
        for (int off = 2; off; off >>= 1) {
            s  += __shfl_xor_sync(0xffffffffu, s,  off);
            ss += __shfl_xor_sync(0xffffffffu, ss, off);
        }
        if (lane == 0) { red0[0] = s; red1[0] = ss; }
    }
    __syncthreads();
    float mean = red0[0] * (1.0f / Dv);
    float var  = red1[0] * (1.0f / Dv) - mean * mean;
    float rstd = rsqrtf(var + 1e-5f);
#pragma unroll
    for (int i = 0; i < 4; i++) {
        int c = tid + i * 128;
        float val = (v[i] - mean) * rstd * gamma[c] + beta[c];
        __nv_bfloat16 hi, lo; bsplit(val, hi, lo);
        g_xlnhi[(size_t)row * Dv + c] = hi;
        g_xlnlo[(size_t)row * Dv + c] = lo;
    }
}

// ---------------- fp32 -> bf16 hi/lo split ----------------
__global__ void split_w(const float* __restrict__ src, __nv_bfloat16* __restrict__ hi,
                        __nv_bfloat16* __restrict__ lo, int n) {
    int i = blockIdx.x * blockDim.x + threadIdx.x;
    if (i < n) { __nv_bfloat16 h, l; bsplit(src[i], h, l); hi[i] = h; lo[i] = l; }
}

// ---------------- head weight prep (pad to 128 rows, split) ----------------
__global__ void head_prep(const float* __restrict__ Wm, const float* __restrict__ Wl,
                          const float* __restrict__ bm, const float* __restrict__ bl) {
    int i = blockIdx.x * blockDim.x + threadIdx.x;
    if (i < NHEAD * Hv) {
        int r = i / Hv;
        float v = 0.f;
        if (r < Av) v = Wm[i];
        else if (r < 2 * Av) v = Wl[i - Av * Hv];
        __nv_bfloat16 h, l; bsplit(v, h, l);
        g_wheadhi[i] = h; g_wheadlo[i] = l;
    }
    if (i < NHEAD) {
        float b = 0.f;
        if (i < Av) b = bm[i];
        else if (i < 2 * Av) b = bl[i - Av];
        g_bheadp[i] = b;
    }
}

// ---------------- mma.sync bf16-split GEMM ----------------
// C(M x N) = (Ahi+Alo)(Bhi+Blo)^T (+bias when blockIdx.z==0), dropping Alo*Blo.
// Block 128x128, BK=16, 8 warps (warp tile 64x32), 4-stage cp.async pipeline.
// blockIdx.z selects a K-slice of length Ktile; output to Cp + z*partStride.
// EPI: 0 = fp32 store, 2 = relu + bf16-split store (Chi/Clo).
#define STG_MAT 6144u        // 128 rows * 48B
#define STG_SZ  24576u       // 4 matrices
#define MG_SMEM (4 * 24576)  // 4 stages

template<int EPI>
__global__ void __launch_bounds__(256, 1) mgemm(
    int K, int Ktile,
    const __nv_bfloat16* __restrict__ Ahi, const __nv_bfloat16* __restrict__ Alo,
    const __nv_bfloat16* __restrict__ Bhi, const __nv_bfloat16* __restrict__ Blo,
    const float* __restrict__ bias,
    float* __restrict__ Cp, int ldc, size_t partStride,
    __nv_bfloat16* __restrict__ Chi, __nv_bfloat16* __restrict__ Clo)
{
    extern __shared__ char smem[];
    const uint32_t sb = smem_u32(smem);
    const int tid = threadIdx.x;
    const int wid = tid >> 5, lane = tid & 31;
    const int bm0 = blockIdx.y * 128, bn0 = blockIdx.x * 128;
    const int kz0 = blockIdx.z * Ktile;
    const int nk = Ktile >> 4;

    // global sources: one 16B chunk per thread per matrix per k-tile
    const int grow = tid >> 1, gch = tid & 1;
    const __nv_bfloat16* gp[4];
    gp[0] = Ahi + (size_t)(bm0 + grow) * K + kz0 + gch * 8;
    gp[1] = Alo + (size_t)(bm0 + grow) * K + kz0 + gch * 8;
    gp[2] = Bhi + (size_t)(bn0 + grow) * K + kz0 + gch * 8;
    gp[3] = Blo + (size_t)(bn0 + grow) * K + kz0 + gch * 8;
    const uint32_t sdst = sb + (uint32_t)grow * 48u + (uint32_t)gch * 16u;

    // prologue: tiles 0,1
#pragma unroll
    for (int it = 0; it < 2; it++) {
        uint32_t s = sdst + (uint32_t)(it & 3) * STG_SZ;
        size_t ko = (size_t)it * 16;
#pragma unroll
        for (int m = 0; m < 4; m++) CP_ASYNC16(s + m * STG_MAT, gp[m] + ko);
        CP_COMMIT();
    }

    // warp tiling
    const int warpM = (wid & 1) * 64;
    const int warpN = (wid >> 1) * 32;
    // ldmatrix lane addresses (offsets within a stage)
    const uint32_t aoff = (uint32_t)(warpM + (lane & 15)) * 48u + (uint32_t)(lane >> 4) * 16u;
    const uint32_t boff = 2u * STG_MAT +
        (uint32_t)(warpN + ((lane >> 4) << 3) + (lane & 7)) * 48u +
        (uint32_t)((lane >> 3) & 1) * 16u;

    float acc[4][4][4];
#pragma unroll
    for (int i = 0; i < 4; i++)
#pragma unroll
        for (int j = 0; j < 4; j++)
#pragma unroll
            for (int q = 0; q < 4; q++) acc[i][j][q] = 0.f;

    for (int it = 0; it < nk; it++) {
        // issue tile it+2
        if (it + 2 < nk) {
            uint32_t s = sdst + (uint32_t)((it + 2) & 3) * STG_SZ;
            size_t ko = (size_t)(it + 2) * 16;
#pragma unroll
            for (int m = 0; m < 4; m++) CP_ASYNC16(s + m * STG_MAT, gp[m] + ko);
        }
        CP_COMMIT();
        CP_WAIT2();
        __syncthreads();

        const uint32_t st = sb + (uint32_t)(it & 3) * STG_SZ;
        uint32_t ah[4][4], al[4][4], bh[2][4], bl[2][4];
#pragma unroll
        for (int mf = 0; mf < 4; mf++) {
            ldsm4(ah[mf], st + aoff + mf * 768u);
            ldsm4(al[mf], st + STG_MAT + aoff + mf * 768u);
        }
#pragma unroll
        for (int p = 0; p < 2; p++) {
            ldsm4(bh[p], st + boff + p * 768u);
            ldsm4(bl[p], st + STG_MAT + boff + p * 768u);
        }
#pragma unroll
        for (int mf = 0; mf < 4; mf++) {
#pragma unroll
            for (int nf = 0; nf < 4; nf++) {
                const int p = nf >> 1, h = (nf & 1) * 2;
                mma_bf16(acc[mf][nf], ah[mf], &bh[p][h]);
                mma_bf16(acc[mf][nf], ah[mf], &bl[p][h]);
                mma_bf16(acc[mf][nf], al[mf], &bh[p][h]);
            }
        }
    }

    // ---- epilogue ----
    const int r = lane >> 2, c2 = (lane & 3) * 2;
#pragma unroll
    for (int mf = 0; mf < 4; mf++) {
#pragma unroll
        for (int nf = 0; nf < 4; nf++) {
            const int row0 = bm0 + warpM + mf * 16 + r;
            const int col  = bn0 + warpN + nf * 8 + c2;
            float b0 = 0.f, b1 = 0.f;
            if (bias != nullptr && blockIdx.z == 0) { b0 = bias[col]; b1 = bias[col + 1]; }
            float v00 = acc[mf][nf][0] + b0, v01 = acc[mf][nf][1] + b1;
            float v10 = acc[mf][nf][2] + b0, v11 = acc[mf][nf][3] + b1;
            if (EPI == 2) {
                v00 = fmaxf(v00, 0.f); v01 = fmaxf(v01, 0.f);
                v10 = fmaxf(v10, 0.f); v11 = fmaxf(v11, 0.f);
                __nv_bfloat16 h0, l0, h1, l1;
                bsplit(v00, h0, l0); bsplit(v01, h1, l1);
                __nv_bfloat162 th; th.x = h0; th.y = h1;
                __nv_bfloat162 tl; tl.x = l0; tl.y = l1;
                *(__nv_bfloat162*)(Chi + (size_t)row0 * ldc + col) = th;
                *(__nv_bfloat162*)(Clo + (size_t)row0 * ldc + col) = tl;
                bsplit(v10, h0, l0); bsplit(v11, h1, l1);
                th.x = h0; th.y = h1; tl.x = l0; tl.y = l1;
                *(__nv_bfloat162*)(Chi + (size_t)(row0 + 8) * ldc + col) = th;
                *(__nv_bfloat162*)(Clo + (size_t)(row0 + 8) * ldc + col) = tl;
            } else {
                float* Co = Cp + blockIdx.z * partStride;
                *(float2*)(Co + (size_t)row0 * ldc + col)       = make_float2(v00, v01);
                *(float2*)(Co + (size_t)(row0 + 8) * ldc + col) = make_float2(v10, v11);
            }
        }
    }
}

// ---------------- GRU gates: fused split-K reduce + elementwise ----------------
__global__ void gru_gates(int t, const int* __restrict__ starts,
                          const float* __restrict__ b_hh) {
    int idx = blockIdx.x * blockDim.x + threadIdx.x;
    if (idx >= Bv * Hv) return;
    int b = idx >> 10, j = idx & 1023;
    size_t xrow = ((size_t)b * Tv + t) * G3;
    float xr = g_xg[xrow + j];
    float xz = g_xg[xrow + Hv + j];
    float xn = g_xg[xrow + 2 * Hv + j];
    const size_t PS = (size_t)Bv * G3;
    size_t grow = (size_t)b * G3;
    float hr = b_hh[j], hz = b_hh[Hv + j], hn = b_hh[2 * Hv + j];
#pragma unroll
    for (int z = 0; z < SKv; z++) {
        hr += g_ghp[z * PS + grow + j];
        hz += g_ghp[z * PS + grow + Hv + j];
        hn += g_ghp[z * PS + grow + 2 * Hv + j];
    }
    float st = (float)starts[b * Tv + t];
    float hm = g_h[idx] * (1.0f - st);
    float r = 1.0f / (1.0f + expf(-(xr + hr)));
    float z = 1.0f / (1.0f + expf(-(xz + hz)));
    float n = tanhf(xn + r * hn);
    float hnew = (1.0f - z) * n + z * hm;
    g_h[idx] = hnew;
    __nv_bfloat16 hh, hl;
    bsplit(hnew, hh, hl);
    g_hseqhi[((size_t)b * Tv + t) * Hv + j] = hh;
    g_hseqlo[((size_t)b * Tv + t) * Hv + j] = hl;
    if (t + 1 < Tv) {
        float st2 = (float)starts[b * Tv + t + 1];
        float hm2 = hnew * (1.0f - st2);
        bsplit(hm2, hh, hl);
        g_hmhi[idx] = hh;
        g_hmlo[idx] = hl;
    }
}

// ---------------- head split + clip ----------------
__global__ void head_split(float* __restrict__ out) {
    int idx = blockIdx.x * blockDim.x + threadIdx.x;   // BT*64
    if (idx >= BT * 64) return;
    int row = idx >> 6, n = idx & 63;
    float v = g_headtmp[(size_t)row * NHEAD + n];
    if (n < Av) {
        out[(size_t)row * Av + n] = v;
    } else {
        v = fminf(fmaxf(v, -20.0f), 2.0f);
        out[(size_t)BT * Av + (size_t)row * Av + (n - Av)] = v;
    }
}

__global__ void init_h(const float* __restrict__ h0, const int* __restrict__ starts) {
    int i = blockIdx.x * blockDim.x + threadIdx.x;
    if (i >= Bv * Hv) return;
    int b = i >> 10;
    float h = h0[i];
    g_h[i] = h;
    float hm = h * (1.0f - (float)starts[b * Tv]);
    __nv_bfloat16 hh, hl; bsplit(hm, hh, hl);
    g_hmhi[i] = hh; g_hmlo[i] = hl;
}
__global__ void emit_h(float* __restrict__ out) {
    int i = blockIdx.x * blockDim.x + threadIdx.x;
    if (i < Bv * Hv) out[i] = g_h[i];
}

extern "C" void kernel_launch(void* const* d_in, const int* in_sizes, int n_in,
                              void* d_out, int out_size) {
    const float* obs    = (const float*)d_in[0];
    const float* h0     = (const float*)d_in[1];
    const int*   starts = (const int*)  d_in[2];
    const float* gamma  = (const float*)d_in[3];
    const float* beta   = (const float*)d_in[4];
    const float* W_fc   = (const float*)d_in[5];
    const float* b_fc   = (const float*)d_in[6];
    const float* W_ih   = (const float*)d_in[7];
    const float* b_ih   = (const float*)d_in[8];
    const float* W_hh   = (const float*)d_in[9];
    const float* b_hh   = (const float*)d_in[10];
    const float* W_out  = (const float*)d_in[11];
    const float* b_out  = (const float*)d_in[12];
    const float* W_mean = (const float*)d_in[13];
    const float* b_mean = (const float*)d_in[14];
    const float* W_ls   = (const float*)d_in[15];
    const float* b_ls   = (const float*)d_in[16];
    float* out = (float*)d_out;

    static bool attr_done = false;
    if (!attr_done) {
        cudaFuncSetAttribute(mgemm<0>, cudaFuncAttributeMaxDynamicSharedMemorySize, MG_SMEM);
        cudaFuncSetAttribute(mgemm<2>, cudaFuncAttributeMaxDynamicSharedMemorySize, MG_SMEM);
        attr_done = true;
    }

    __nv_bfloat16 *xlnhi, *xlnlo, *xhi, *xlo, *hseqhi, *hseqlo, *featshi, *featslo;
    __nv_bfloat16 *hmhi, *hmlo, *wfchi, *wfclo, *wihhi, *wihlo, *whhhi, *whhlo;
    __nv_bfloat16 *wouthi, *woutlo, *wheadhi, *wheadlo;
    float *xg, *ghp, *headtmp, *bheadp;
    cudaGetSymbolAddress((void**)&xlnhi, g_xlnhi);   cudaGetSymbolAddress((void**)&xlnlo, g_xlnlo);
    cudaGetSymbolAddress((void**)&xhi, g_xhi);       cudaGetSymbolAddress((void**)&xlo, g_xlo);
    cudaGetSymbolAddress((void**)&xg, g_xg);
    cudaGetSymbolAddress((void**)&hseqhi, g_hseqhi); cudaGetSymbolAddress((void**)&hseqlo, g_hseqlo);
    cudaGetSymbolAddress((void**)&featshi, g_featshi); cudaGetSymbolAddress((void**)&featslo, g_featslo);
    cudaGetSymbolAddress((void**)&ghp, g_ghp);
    cudaGetSymbolAddress((void**)&hmhi, g_hmhi);     cudaGetSymbolAddress((void**)&hmlo, g_hmlo);
    cudaGetSymbolAddress((void**)&headtmp, g_headtmp);
    cudaGetSymbolAddress((void**)&wfchi, g_wfchi);   cudaGetSymbolAddress((void**)&wfclo, g_wfclo);
    cudaGetSymbolAddress((void**)&wihhi, g_wihhi);   cudaGetSymbolAddress((void**)&wihlo, g_wihlo);
    cudaGetSymbolAddress((void**)&whhhi, g_whhhi);   cudaGetSymbolAddress((void**)&whhlo, g_whhlo);
    cudaGetSymbolAddress((void**)&wouthi, g_wouthi); cudaGetSymbolAddress((void**)&woutlo, g_woutlo);
    cudaGetSymbolAddress((void**)&wheadhi, g_wheadhi); cudaGetSymbolAddress((void**)&wheadlo, g_wheadlo);
    cudaGetSymbolAddress((void**)&bheadp, g_bheadp);

    // 1. LayerNorm -> bf16 split
    ln_kernel<<<BT, 128>>>(obs, gamma, beta);

    // weight splits
    split_w<<<(FCv * Dv + 255) / 256, 256>>>(W_fc, wfchi, wfclo, FCv * Dv);
    split_w<<<(G3 * FCv + 255) / 256, 256>>>(W_ih, wihhi, wihlo, G3 * FCv);
    split_w<<<(G3 * Hv + 255) / 256, 256>>>(W_hh, whhhi, whhlo, G3 * Hv);
    split_w<<<(Hv * Hv + 255) / 256, 256>>>(W_out, wouthi, woutlo, Hv * Hv);
    head_prep<<<(NHEAD * Hv + 255) / 256, 256>>>(W_mean, W_ls, b_mean, b_ls);

    // 2. FC: x = relu(xln @ W_fc^T + b_fc) -> bf16 split
    mgemm<2><<<dim3(FCv / 128, BT / 128, 1), 256, MG_SMEM>>>(
        Dv, Dv, xlnhi, xlnlo, wfchi, wfclo, b_fc, nullptr, FCv, 0, xhi, xlo);

    // 3. xg = x @ W_ih^T + b_ih (fp32)
    mgemm<0><<<dim3(G3 / 128, BT / 128, 1), 256, MG_SMEM>>>(
        FCv, FCv, xhi, xlo, wihhi, wihlo, b_ih, xg, G3, 0, nullptr, nullptr);

    // 4. GRU scan (split-K=4 step GEMM, bias folded into gates)
    init_h<<<(Bv * Hv + 255) / 256, 256>>>(h0, starts);
    const size_t PS = (size_t)Bv * G3;
    for (int t = 0; t < Tv; t++) {
        mgemm<0><<<dim3(G3 / 128, Bv / 128, SKv), 256, MG_SMEM>>>(
            Hv, Hv / SKv, hmhi, hmlo, whhhi, whhlo, nullptr, ghp, G3, PS, nullptr, nullptr);
        gru_gates<<<(Bv * Hv + 255) / 256, 256>>>(t, starts, b_hh);
    }

    // 5. feats = relu(hseq @ W_out^T + b_out) -> bf16 split
    mgemm<2><<<dim3(Hv / 128, BT / 128, 1), 256, MG_SMEM>>>(
        Hv, Hv, hseqhi, hseqlo, wouthi, woutlo, b_out, nullptr, Hv, 0, featshi, featslo);

    // 6. heads (N padded to 128)
    mgemm<0><<<dim3(1, BT / 128, 1), 256, MG_SMEM>>>(
        Hv, Hv, featshi, featslo, wheadhi, wheadlo, bheadp, headtmp, NHEAD, 0, nullptr, nullptr);
    head_split<<<(BT * 64 + 255) / 256, 256>>>(out);

    // 7. h_final
    emit_h<<<(Bv * Hv + 255) / 256, 256>>>(out + 2 * (size_t)BT * Av);
}

// round 5
// speedup vs baseline: 5.3365x; 1.0136x over previous
#include <cuda_runtime.h>
#include <cuda_bf16.h>
#include <cstdint>
#include <math.h>

#define Bv 256
#define Tv 128
#define Dv 512
#define Hv 1024
#define FCv 1024
#define Av 32
#define BT (Bv*Tv)      // 32768
#define G3 (3*Hv)       // 3072
#define NHEAD 128       // padded head output cols
#define SKv 4           // split-K for the step GEMM
#define GRP 16          // scan steps per overlap group
#define NG  (Tv/GRP)    // 8 groups
#define GROWS (Bv*GRP)  // 4096 rows per group (time-major)

// ---------------- scratch (static device globals; no allocs) ----------------
__device__ __nv_bfloat16 g_xlnhi[(size_t)BT*Dv],  g_xlnlo[(size_t)BT*Dv];
__device__ __nv_bfloat16 g_xhi[(size_t)BT*FCv],   g_xlo[(size_t)BT*FCv];
__device__ float         g_xg[(size_t)BT*G3];          // time-major rows (t*Bv+b)
__device__ __nv_bfloat16 g_hseqhi[(size_t)BT*Hv], g_hseqlo[(size_t)BT*Hv];   // time-major
__device__ __nv_bfloat16 g_featshi[(size_t)BT*Hv],g_featslo[(size_t)BT*Hv];  // time-major
__device__ float         g_h[Bv*Hv];
__device__ float         g_ghp[(size_t)SKv*Bv*G3];   // split-K partials
__device__ __nv_bfloat16 g_hmhi[Bv*Hv], g_hmlo[Bv*Hv];
__device__ float         g_headtmp[(size_t)BT*NHEAD];  // time-major
// split weights
__device__ __nv_bfloat16 g_wfchi[FCv*Dv],  g_wfclo[FCv*Dv];
__device__ __nv_bfloat16 g_wihhi[G3*FCv],  g_wihlo[G3*FCv];
__device__ __nv_bfloat16 g_whhhi[G3*Hv],   g_whhlo[G3*Hv];
__device__ __nv_bfloat16 g_wouthi[Hv*Hv],  g_woutlo[Hv*Hv];
__device__ __nv_bfloat16 g_wheadhi[NHEAD*Hv], g_wheadlo[NHEAD*Hv];
__device__ float         g_bheadp[NHEAD];

// ---------------- helpers ----------------
__device__ __forceinline__ uint32_t smem_u32(const void* p) {
    uint32_t a;
    asm("{ .reg .u64 t; cvta.to.shared.u64 t, %1; cvt.u32.u64 %0, t; }" : "=r"(a) : "l"(p));
    return a;
}
#define CP_ASYNC16(s, g) \
    asm volatile("cp.async.cg.shared.global [%0], [%1], 16;" :: "r"(s), "l"(g) : "memory")
#define CP_COMMIT() asm volatile("cp.async.commit_group;" ::: "memory")
#define CP_WAIT2()  asm volatile("cp.async.wait_group 2;" ::: "memory")

__device__ __forceinline__ void ldsm4(uint32_t* r, uint32_t addr) {
    asm volatile("ldmatrix.sync.aligned.m8n8.x4.shared.b16 {%0,%1,%2,%3}, [%4];"
        : "=r"(r[0]), "=r"(r[1]), "=r"(r[2]), "=r"(r[3]) : "r"(addr));
}
__device__ __forceinline__ void mma_bf16(float* d, const uint32_t* a, const uint32_t* b) {
    asm volatile("mma.sync.aligned.m16n8k16.row.col.f32.bf16.bf16.f32 "
        "{%0,%1,%2,%3}, {%4,%5,%6,%7}, {%8,%9}, {%0,%1,%2,%3};"
        : "+f"(d[0]), "+f"(d[1]), "+f"(d[2]), "+f"(d[3])
        : "r"(a[0]), "r"(a[1]), "r"(a[2]), "r"(a[3]), "r"(b[0]), "r"(b[1]));
}
__device__ __forceinline__ void bsplit(float v, __nv_bfloat16& hi, __nv_bfloat16& lo) {
    hi = __float2bfloat16(v);
    lo = __float2bfloat16(v - __bfloat162float(hi));
}

// ---------------- LayerNorm over D=512, emits bf16 split ----------------
__global__ void ln_kernel(const float* __restrict__ obs,
                          const float* __restrict__ gamma,
                          const float* __restrict__ beta) {
    int row = blockIdx.x;
    int tid = threadIdx.x;             // 128 threads
    const float* o = obs + (size_t)row * Dv;
    float v[4];
    float s = 0.f, ss = 0.f;
#pragma unroll
    for (int i = 0; i < 4; i++) {
        v[i] = o[tid + i * 128];
        s += v[i]; ss += v[i] * v[i];
    }
    __shared__ float red0[32], red1[32];
    for (int off = 16; off; off >>= 1) {
        s  += __shfl_xor_sync(0xffffffffu, s,  off);
        ss += __shfl_xor_sync(0xffffffffu, ss, off);
    }
    int warp = tid >> 5, lane = tid & 31;
    if (lane == 0) { red0[warp] = s; red1[warp] = ss; }
    __syncthreads();
    if (warp == 0) {
        s  = (lane < 4) ? red0[lane] : 0.f;
        ss = (lane < 4) ? red1[lane] : 0.f;
        for (int off = 2; off; off >>= 1) {
            s  += __shfl_xor_sync(0xffffffffu, s,  off);
            ss += __shfl_xor_sync(0xffffffffu, ss, off);
        }
        if (lane == 0) { red0[0] = s; red1[0] = ss; }
    }
    __syncthreads();
    float mean = red0[0] * (1.0f / Dv);
    float var  = red1[0] * (1.0f / Dv) - mean * mean;
    float rstd = rsqrtf(var + 1e-5f);
#pragma unroll
    for (int i = 0; i < 4; i++) {
        int c = tid + i * 128;
        float val = (v[i] - mean) * rstd * gamma[c] + beta[c];
        __nv_bfloat16 hi, lo; bsplit(val, hi, lo);
        g_xlnhi[(size_t)row * Dv + c] = hi;
        g_xlnlo[(size_t)row * Dv + c] = lo;
    }
}

// ---------------- fp32 -> bf16 hi/lo split ----------------
__global__ void split_w(const float* __restrict__ src, __nv_bfloat16* __restrict__ hi,
                        __nv_bfloat16* __restrict__ lo, int n) {
    int i = blockIdx.x * blockDim.x + threadIdx.x;
    if (i < n) { __nv_bfloat16 h, l; bsplit(src[i], h, l); hi[i] = h; lo[i] = l; }
}

// ---------------- head weight prep (pad to 128 rows, split) ----------------
__global__ void head_prep(const float* __restrict__ Wm, const float* __restrict__ Wl,
                          const float* __restrict__ bm, const float* __restrict__ bl) {
    int i = blockIdx.x * blockDim.x + threadIdx.x;
    if (i < NHEAD * Hv) {
        int r = i / Hv;
        float v = 0.f;
        if (r < Av) v = Wm[i];
        else if (r < 2 * Av) v = Wl[i - Av * Hv];
        __nv_bfloat16 h, l; bsplit(v, h, l);
        g_wheadhi[i] = h; g_wheadlo[i] = l;
    }
    if (i < NHEAD) {
        float b = 0.f;
        if (i < Av) b = bm[i];
        else if (i < 2 * Av) b = bl[i - Av];
        g_bheadp[i] = b;
    }
}

// ---------------- mma.sync bf16-split GEMM ----------------
// C(rows x N) = (Ahi+Alo)(Bhi+Blo)^T (+bias when z==0), dropping Alo*Blo.
// Block 128x128, BK=16, 8 warps (warp tile 64x32), 4-stage cp.async pipeline.
// rowOff: block row offset (C rows at rowOff + by*128).
// PERM=1: A input row = time-major->batch-major map ((r&255)<<7)+(r>>8).
// blockIdx.z: K-slice of length Ktile; fp32 output to Cp + z*partStride.
// EPI: 0 = fp32 store, 2 = relu + bf16-split store (Chi/Clo).
#define STG_MAT 6144u        // 128 rows * 48B
#define STG_SZ  24576u       // 4 matrices
#define MG_SMEM (4 * 24576)  // 4 stages

template<int EPI, int PERM, int MINB>
__global__ void __launch_bounds__(256, MINB) mgemm(
    int K, int Ktile, int rowOff,
    const __nv_bfloat16* __restrict__ Ahi, const __nv_bfloat16* __restrict__ Alo,
    const __nv_bfloat16* __restrict__ Bhi, const __nv_bfloat16* __restrict__ Blo,
    const float* __restrict__ bias,
    float* __restrict__ Cp, int ldc, size_t partStride,
    __nv_bfloat16* __restrict__ Chi, __nv_bfloat16* __restrict__ Clo)
{
    extern __shared__ char smem[];
    const uint32_t sb = smem_u32(smem);
    const int tid = threadIdx.x;
    const int wid = tid >> 5, lane = tid & 31;
    const int bm0 = rowOff + blockIdx.y * 128, bn0 = blockIdx.x * 128;
    const int kz0 = blockIdx.z * Ktile;
    const int nk = Ktile >> 4;

    // global sources: one 16B chunk per thread per matrix per k-tile
    const int grow = tid >> 1, gch = tid & 1;
    const int growG = bm0 + grow;
    const int arow = PERM ? (((growG & 255) << 7) + (growG >> 8)) : growG;
    const __nv_bfloat16* gp[4];
    gp[0] = Ahi + (size_t)arow * K + kz0 + gch * 8;
    gp[1] = Alo + (size_t)arow * K + kz0 + gch * 8;
    gp[2] = Bhi + (size_t)(bn0 + grow) * K + kz0 + gch * 8;
    gp[3] = Blo + (size_t)(bn0 + grow) * K + kz0 + gch * 8;
    const uint32_t sdst = sb + (uint32_t)grow * 48u + (uint32_t)gch * 16u;

    // prologue: tiles 0,1
#pragma unroll
    for (int it = 0; it < 2; it++) {
        uint32_t s = sdst + (uint32_t)(it & 3) * STG_SZ;
        size_t ko = (size_t)it * 16;
#pragma unroll
        for (int m = 0; m < 4; m++) CP_ASYNC16(s + m * STG_MAT, gp[m] + ko);
        CP_COMMIT();
    }

    // warp tiling
    const int warpM = (wid & 1) * 64;
    const int warpN = (wid >> 1) * 32;
    const uint32_t aoff = (uint32_t)(warpM + (lane & 15)) * 48u + (uint32_t)(lane >> 4) * 16u;
    const uint32_t boff = 2u * STG_MAT +
        (uint32_t)(warpN + ((lane >> 4) << 3) + (lane & 7)) * 48u +
        (uint32_t)((lane >> 3) & 1) * 16u;

    float acc[4][4][4];
#pragma unroll
    for (int i = 0; i < 4; i++)
#pragma unroll
        for (int j = 0; j < 4; j++)
#pragma unroll
            for (int q = 0; q < 4; q++) acc[i][j][q] = 0.f;

    for (int it = 0; it < nk; it++) {
        if (it + 2 < nk) {
            uint32_t s = sdst + (uint32_t)((it + 2) & 3) * STG_SZ;
            size_t ko = (size_t)(it + 2) * 16;
#pragma unroll
            for (int m = 0; m < 4; m++) CP_ASYNC16(s + m * STG_MAT, gp[m] + ko);
        }
        CP_COMMIT();
        CP_WAIT2();
        __syncthreads();

        const uint32_t st = sb + (uint32_t)(it & 3) * STG_SZ;
        uint32_t ah[4][4], al[4][4], bh[2][4], bl[2][4];
#pragma unroll
        for (int mf = 0; mf < 4; mf++) {
            ldsm4(ah[mf], st + aoff + mf * 768u);
            ldsm4(al[mf], st + STG_MAT + aoff + mf * 768u);
        }
#pragma unroll
        for (int p = 0; p < 2; p++) {
            ldsm4(bh[p], st + boff + p * 768u);
            ldsm4(bl[p], st + STG_MAT + boff + p * 768u);
        }
#pragma unroll
        for (int mf = 0; mf < 4; mf++) {
#pragma unroll
            for (int nf = 0; nf < 4; nf++) {
                const int p = nf >> 1, h = (nf & 1) * 2;
                mma_bf16(acc[mf][nf], ah[mf], &bh[p][h]);
                mma_bf16(acc[mf][nf], ah[mf], &bl[p][h]);
                mma_bf16(acc[mf][nf], al[mf], &bh[p][h]);
            }
        }
    }

    // ---- epilogue ----
    const int r = lane >> 2, c2 = (lane & 3) * 2;
#pragma unroll
    for (int mf = 0; mf < 4; mf++) {
#pragma unroll
        for (int nf = 0; nf < 4; nf++) {
            const int row0 = bm0 + warpM + mf * 16 + r;
            const int col  = bn0 + warpN + nf * 8 + c2;
            float b0 = 0.f, b1 = 0.f;
            if (bias != nullptr && blockIdx.z == 0) { b0 = bias[col]; b1 = bias[col + 1]; }
            float v00 = acc[mf][nf][0] + b0, v01 = acc[mf][nf][1] + b1;
            float v10 = acc[mf][nf][2] + b0, v11 = acc[mf][nf][3] + b1;
            if (EPI == 2) {
                v00 = fmaxf(v00, 0.f); v01 = fmaxf(v01, 0.f);
                v10 = fmaxf(v10, 0.f); v11 = fmaxf(v11, 0.f);
                __nv_bfloat16 h0, l0, h1, l1;
                bsplit(v00, h0, l0); bsplit(v01, h1, l1);
                __nv_bfloat162 th; th.x = h0; th.y = h1;
                __nv_bfloat162 tl; tl.x = l0; tl.y = l1;
                *(__nv_bfloat162*)(Chi + (size_t)row0 * ldc + col) = th;
                *(__nv_bfloat162*)(Clo + (size_t)row0 * ldc + col) = tl;
                bsplit(v10, h0, l0); bsplit(v11, h1, l1);
                th.x = h0; th.y = h1; tl.x = l0; tl.y = l1;
                *(__nv_bfloat162*)(Chi + (size_t)(row0 + 8) * ldc + col) = th;
                *(__nv_bfloat162*)(Clo + (size_t)(row0 + 8) * ldc + col) = tl;
            } else {
                float* Co = Cp + blockIdx.z * partStride;
                *(float2*)(Co + (size_t)row0 * ldc + col)       = make_float2(v00, v01);
                *(float2*)(Co + (size_t)(row0 + 8) * ldc + col) = make_float2(v10, v11);
            }
        }
    }
}

// ---------------- GRU gates: fused split-K reduce + elementwise ----------------
// xg / hseq are time-major (row = t*Bv + b)
__global__ void gru_gates(int t, const int* __restrict__ starts,
                          const float* __restrict__ b_hh) {
    int idx = blockIdx.x * blockDim.x + threadIdx.x;
    if (idx >= Bv * Hv) return;
    int b = idx >> 10, j = idx & 1023;
    size_t xrow = ((size_t)t * Bv + b) * G3;
    float xr = g_xg[xrow + j];
    float xz = g_xg[xrow + Hv + j];
    float xn = g_xg[xrow + 2 * Hv + j];
    const size_t PS = (size_t)Bv * G3;
    size_t grow = (size_t)b * G3;
    float hr = b_hh[j], hz = b_hh[Hv + j], hn = b_hh[2 * Hv + j];
#pragma unroll
    for (int z = 0; z < SKv; z++) {
        hr += g_ghp[z * PS + grow + j];
        hz += g_ghp[z * PS + grow + Hv + j];
        hn += g_ghp[z * PS + grow + 2 * Hv + j];
    }
    float st = (float)starts[b * Tv + t];
    float hm = g_h[idx] * (1.0f - st);
    float r = 1.0f / (1.0f + expf(-(xr + hr)));
    float z = 1.0f / (1.0f + expf(-(xz + hz)));
    float n = tanhf(xn + r * hn);
    float hnew = (1.0f - z) * n + z * hm;
    g_h[idx] = hnew;
    __nv_bfloat16 hh, hl;
    bsplit(hnew, hh, hl);
    g_hseqhi[((size_t)t * Bv + b) * Hv + j] = hh;
    g_hseqlo[((size_t)t * Bv + b) * Hv + j] = hl;
    if (t + 1 < Tv) {
        float st2 = (float)starts[b * Tv + t + 1];
        float hm2 = hnew * (1.0f - st2);
        bsplit(hm2, hh, hl);
        g_hmhi[idx] = hh;
        g_hmlo[idx] = hl;
    }
}

// ---------------- head split + clip (per group, time-major source) ----------------
__global__ void head_split(int rowOff, float* __restrict__ out) {
    int idx = blockIdx.x * blockDim.x + threadIdx.x;   // GROWS*64
    if (idx >= GROWS * 64) return;
    int row = rowOff + (idx >> 6), n = idx & 63;       // time-major row
    int t = row >> 8, b = row & 255;
    float v = g_headtmp[(size_t)row * NHEAD + n];
    if (n < Av) {
        out[((size_t)b * Tv + t) * Av + n] = v;
    } else {
        v = fminf(fmaxf(v, -20.0f), 2.0f);
        out[(size_t)BT * Av + ((size_t)b * Tv + t) * Av + (n - Av)] = v;
    }
}

__global__ void init_h(const float* __restrict__ h0, const int* __restrict__ starts) {
    int i = blockIdx.x * blockDim.x + threadIdx.x;
    if (i >= Bv * Hv) return;
    int b = i >> 10;
    float h = h0[i];
    g_h[i] = h;
    float hm = h * (1.0f - (float)starts[b * Tv]);
    __nv_bfloat16 hh, hl; bsplit(hm, hh, hl);
    g_hmhi[i] = hh; g_hmlo[i] = hl;
}
__global__ void emit_h(float* __restrict__ out) {
    int i = blockIdx.x * blockDim.x + threadIdx.x;
    if (i < Bv * Hv) out[i] = g_h[i];
}

extern "C" void kernel_launch(void* const* d_in, const int* in_sizes, int n_in,
                              void* d_out, int out_size) {
    const float* obs    = (const float*)d_in[0];
    const float* h0     = (const float*)d_in[1];
    const int*   starts = (const int*)  d_in[2];
    const float* gamma  = (const float*)d_in[3];
    const float* beta   = (const float*)d_in[4];
    const float* W_fc   = (const float*)d_in[5];
    const float* b_fc   = (const float*)d_in[6];
    const float* W_ih   = (const float*)d_in[7];
    const float* b_ih   = (const float*)d_in[8];
    const float* W_hh   = (const float*)d_in[9];
    const float* b_hh   = (const float*)d_in[10];
    const float* W_out  = (const float*)d_in[11];
    const float* b_out  = (const float*)d_in[12];
    const float* W_mean = (const float*)d_in[13];
    const float* b_mean = (const float*)d_in[14];
    const float* W_ls   = (const float*)d_in[15];
    const float* b_ls   = (const float*)d_in[16];
    float* out = (float*)d_out;

    static cudaStream_t s1 = nullptr, s2 = nullptr;
    static cudaEvent_t evStart, evFC, evW, evJoin2;
    static cudaEvent_t evx[NG], evh[NG];
    static bool init_done = false;
    if (!init_done) {
        cudaFuncSetAttribute(mgemm<0, 0, 1>, cudaFuncAttributeMaxDynamicSharedMemorySize, MG_SMEM);
        cudaFuncSetAttribute(mgemm<0, 0, 2>, cudaFuncAttributeMaxDynamicSharedMemorySize, MG_SMEM);
        cudaFuncSetAttribute(mgemm<0, 1, 1>, cudaFuncAttributeMaxDynamicSharedMemorySize, MG_SMEM);
        cudaFuncSetAttribute(mgemm<2, 0, 1>, cudaFuncAttributeMaxDynamicSharedMemorySize, MG_SMEM);
        cudaStreamCreateWithFlags(&s1, cudaStreamNonBlocking);
        cudaStreamCreateWithFlags(&s2, cudaStreamNonBlocking);
        cudaEventCreateWithFlags(&evStart, cudaEventDisableTiming);
        cudaEventCreateWithFlags(&evFC, cudaEventDisableTiming);
        cudaEventCreateWithFlags(&evW, cudaEventDisableTiming);
        cudaEventCreateWithFlags(&evJoin2, cudaEventDisableTiming);
        for (int g = 0; g < NG; g++) {
            cudaEventCreateWithFlags(&evx[g], cudaEventDisableTiming);
            cudaEventCreateWithFlags(&evh[g], cudaEventDisableTiming);
        }
        init_done = true;
    }

    __nv_bfloat16 *xlnhi, *xlnlo, *xhi, *xlo, *hseqhi, *hseqlo, *featshi, *featslo;
    __nv_bfloat16 *hmhi, *hmlo, *wfchi, *wfclo, *wihhi, *wihlo, *whhhi, *whhlo;
    __nv_bfloat16 *wouthi, *woutlo, *wheadhi, *wheadlo;
    float *xg, *ghp, *headtmp, *bheadp;
    cudaGetSymbolAddress((void**)&xlnhi, g_xlnhi);   cudaGetSymbolAddress((void**)&xlnlo, g_xlnlo);
    cudaGetSymbolAddress((void**)&xhi, g_xhi);       cudaGetSymbolAddress((void**)&xlo, g_xlo);
    cudaGetSymbolAddress((void**)&xg, g_xg);
    cudaGetSymbolAddress((void**)&hseqhi, g_hseqhi); cudaGetSymbolAddress((void**)&hseqlo, g_hseqlo);
    cudaGetSymbolAddress((void**)&featshi, g_featshi); cudaGetSymbolAddress((void**)&featslo, g_featslo);
    cudaGetSymbolAddress((void**)&ghp, g_ghp);
    cudaGetSymbolAddress((void**)&hmhi, g_hmhi);     cudaGetSymbolAddress((void**)&hmlo, g_hmlo);
    cudaGetSymbolAddress((void**)&headtmp, g_headtmp);
    cudaGetSymbolAddress((void**)&wfchi, g_wfchi);   cudaGetSymbolAddress((void**)&wfclo, g_wfclo);
    cudaGetSymbolAddress((void**)&wihhi, g_wihhi);   cudaGetSymbolAddress((void**)&wihlo, g_wihlo);
    cudaGetSymbolAddress((void**)&whhhi, g_whhhi);   cudaGetSymbolAddress((void**)&whhlo, g_whhlo);
    cudaGetSymbolAddress((void**)&wouthi, g_wouthi); cudaGetSymbolAddress((void**)&woutlo, g_woutlo);
    cudaGetSymbolAddress((void**)&wheadhi, g_wheadhi); cudaGetSymbolAddress((void**)&wheadlo, g_wheadlo);
    cudaGetSymbolAddress((void**)&bheadp, g_bheadp);

    const size_t PS = (size_t)Bv * G3;

    // ---- fork ----
    cudaEventRecord(evStart, 0);
    cudaStreamWaitEvent(s1, evStart, 0);
    cudaStreamWaitEvent(s2, evStart, 0);

    // ---- s1: late-stage weight prep (wout, whead) ----
    split_w<<<(Hv * Hv + 255) / 256, 256, 0, s1>>>(W_out, wouthi, woutlo, Hv * Hv);
    head_prep<<<(NHEAD * Hv + 255) / 256, 256, 0, s1>>>(W_mean, W_ls, b_mean, b_ls);
    cudaEventRecord(evW, s1);

    // ---- s0: LN, FC ----
    split_w<<<(FCv * Dv + 255) / 256, 256>>>(W_fc, wfchi, wfclo, FCv * Dv);
    split_w<<<(G3 * FCv + 255) / 256, 256>>>(W_ih, wihhi, wihlo, G3 * FCv);
    ln_kernel<<<BT, 128>>>(obs, gamma, beta);
    mgemm<2, 0, 1><<<dim3(FCv / 128, BT / 128, 1), 256, MG_SMEM>>>(
        Dv, Dv, 0, xlnhi, xlnlo, wfchi, wfclo, b_fc, nullptr, FCv, 0, xhi, xlo);
    cudaEventRecord(evFC, 0);

    // ---- s1: xg production in NG chunks (time-major out, PERM on A rows) ----
    cudaStreamWaitEvent(s1, evFC, 0);
    for (int g = 0; g < NG; g++) {
        mgemm<0, 1, 1><<<dim3(G3 / 128, GROWS / 128, 1), 256, MG_SMEM, s1>>>(
            FCv, FCv, g * GROWS, xhi, xlo, wihhi, wihlo, b_ih, xg, G3, 0, nullptr, nullptr);
        cudaEventRecord(evx[g], s1);
    }

    // ---- s0: scan prerequisites + scan ----
    split_w<<<(G3 * Hv + 255) / 256, 256>>>(W_hh, whhhi, whhlo, G3 * Hv);
    init_h<<<(Bv * Hv + 255) / 256, 256>>>(h0, starts);
    for (int g = 0; g < NG; g++) {
        cudaStreamWaitEvent(0, evx[g], 0);
        for (int tt = 0; tt < GRP; tt++) {
            int t = g * GRP + tt;
            mgemm<0, 0, 2><<<dim3(G3 / 128, Bv / 128, SKv), 256, MG_SMEM>>>(
                Hv, Hv / SKv, 0, hmhi, hmlo, whhhi, whhlo, nullptr, ghp, G3, PS, nullptr, nullptr);
            gru_gates<<<(Bv * Hv + 255) / 256, 256>>>(t, starts, b_hh);
        }
        cudaEventRecord(evh[g], 0);
    }
    emit_h<<<(Bv * Hv + 255) / 256, 256>>>(out + 2 * (size_t)BT * Av);

    // ---- s2: out-projection + heads per group ----
    cudaStreamWaitEvent(s2, evW, 0);
    for (int g = 0; g < NG; g++) {
        cudaStreamWaitEvent(s2, evh[g], 0);
        mgemm<2, 0, 1><<<dim3(Hv / 128, GROWS / 128, 1), 256, MG_SMEM, s2>>>(
            Hv, Hv, g * GROWS, hseqhi, hseqlo, wouthi, woutlo, b_out, nullptr, Hv, 0, featshi, featslo);
        mgemm<0, 0, 1><<<dim3(1, GROWS / 128, 1), 256, MG_SMEM, s2>>>(
            Hv, Hv, g * GROWS, featshi, featslo, wheadhi, wheadlo, bheadp, headtmp, NHEAD, 0, nullptr, nullptr);
        head_split<<<(GROWS * 64 + 255) / 256, 256, 0, s2>>>(g * GROWS, out);
    }
    cudaEventRecord(evJoin2, s2);

    // ---- join ----
    cudaStreamWaitEvent(0, evJoin2, 0);
}

// round 6
// speedup vs baseline: 6.1568x; 1.1537x over previous
#include <cuda_runtime.h>
#include <cuda_bf16.h>
#include <cstdint>
#include <math.h>

#define Bv 256
#define Tv 128
#define Dv 512
#define Hv 1024
#define FCv 1024
#define Av 32
#define BT (Bv*Tv)      // 32768
#define G3 (3*Hv)       // 3072
#define NHEAD 128       // padded head output cols
#define SKv 3           // split-K for the step GEMM (slices 352/336/336)
#define GRP 16          // scan steps per overlap group
#define NG  (Tv/GRP)    // 8 groups
#define GROWS (Bv*GRP)  // 4096 rows per group (time-major)

// ---------------- scratch (static device globals; no allocs) ----------------
__device__ __nv_bfloat16 g_xlnhi[(size_t)BT*Dv],  g_xlnlo[(size_t)BT*Dv];
__device__ __nv_bfloat16 g_xhi[(size_t)BT*FCv],   g_xlo[(size_t)BT*FCv];
__device__ float         g_xg[(size_t)BT*G3];          // time-major rows (t*Bv+b)
__device__ __nv_bfloat16 g_hseqhi[(size_t)BT*Hv], g_hseqlo[(size_t)BT*Hv];   // time-major
__device__ __nv_bfloat16 g_featshi[(size_t)BT*Hv],g_featslo[(size_t)BT*Hv];  // time-major
__device__ float         g_h[Bv*Hv];
__device__ float         g_ghp[(size_t)SKv*Bv*G3];   // split-K partials
__device__ __nv_bfloat16 g_hmhi[Bv*Hv], g_hmlo[Bv*Hv];
__device__ float         g_headtmp[(size_t)BT*NHEAD];  // time-major
// split weights
__device__ __nv_bfloat16 g_wfchi[FCv*Dv],  g_wfclo[FCv*Dv];
__device__ __nv_bfloat16 g_wihhi[G3*FCv],  g_wihlo[G3*FCv];
__device__ __nv_bfloat16 g_whhhi[G3*Hv],   g_whhlo[G3*Hv];
__device__ __nv_bfloat16 g_wouthi[Hv*Hv],  g_woutlo[Hv*Hv];
__device__ __nv_bfloat16 g_wheadhi[NHEAD*Hv], g_wheadlo[NHEAD*Hv];
__device__ float         g_bheadp[NHEAD];

// ---------------- helpers ----------------
__device__ __forceinline__ uint32_t smem_u32(const void* p) {
    uint32_t a;
    asm("{ .reg .u64 t; cvta.to.shared.u64 t, %1; cvt.u32.u64 %0, t; }" : "=r"(a) : "l"(p));
    return a;
}
#define CP_ASYNC16(s, g) \
    asm volatile("cp.async.cg.shared.global [%0], [%1], 16;" :: "r"(s), "l"(g) : "memory")
#define CP_COMMIT() asm volatile("cp.async.commit_group;" ::: "memory")
#define CP_WAIT2()  asm volatile("cp.async.wait_group 2;" ::: "memory")

__device__ __forceinline__ void ldsm4(uint32_t* r, uint32_t addr) {
    asm volatile("ldmatrix.sync.aligned.m8n8.x4.shared.b16 {%0,%1,%2,%3}, [%4];"
        : "=r"(r[0]), "=r"(r[1]), "=r"(r[2]), "=r"(r[3]) : "r"(addr));
}
__device__ __forceinline__ void mma_bf16(float* d, const uint32_t* a, const uint32_t* b) {
    asm volatile("mma.sync.aligned.m16n8k16.row.col.f32.bf16.bf16.f32 "
        "{%0,%1,%2,%3}, {%4,%5,%6,%7}, {%8,%9}, {%0,%1,%2,%3};"
        : "+f"(d[0]), "+f"(d[1]), "+f"(d[2]), "+f"(d[3])
        : "r"(a[0]), "r"(a[1]), "r"(a[2]), "r"(a[3]), "r"(b[0]), "r"(b[1]));
}
__device__ __forceinline__ void bsplit(float v, __nv_bfloat16& hi, __nv_bfloat16& lo) {
    hi = __float2bfloat16(v);
    lo = __float2bfloat16(v - __bfloat162float(hi));
}

// ---------------- LayerNorm over D=512, emits bf16 split ----------------
__global__ void ln_kernel(const float* __restrict__ obs,
                          const float* __restrict__ gamma,
                          const float* __restrict__ beta) {
    int row = blockIdx.x;
    int tid = threadIdx.x;             // 128 threads
    const float* o = obs + (size_t)row * Dv;
    float4 vv = *(const float4*)(o + tid * 4);
    float s = vv.x + vv.y + vv.z + vv.w;
    float ss = vv.x * vv.x + vv.y * vv.y + vv.z * vv.z + vv.w * vv.w;
    __shared__ float red0[32], red1[32];
    for (int off = 16; off; off >>= 1) {
        s  += __shfl_xor_sync(0xffffffffu, s,  off);
        ss += __shfl_xor_sync(0xffffffffu, ss, off);
    }
    int warp = tid >> 5, lane = tid & 31;
    if (lane == 0) { red0[warp] = s; red1[warp] = ss; }
    __syncthreads();
    if (warp == 0) {
        s  = (lane < 4) ? red0[lane] : 0.f;
        ss = (lane < 4) ? red1[lane] : 0.f;
        for (int off = 2; off; off >>= 1) {
            s  += __shfl_xor_sync(0xffffffffu, s,  off);
            ss += __shfl_xor_sync(0xffffffffu, ss, off);
        }
        if (lane == 0) { red0[0] = s; red1[0] = ss; }
    }
    __syncthreads();
    float mean = red0[0] * (1.0f / Dv);
    float var  = red1[0] * (1.0f / Dv) - mean * mean;
    float rstd = rsqrtf(var + 1e-5f);
    float vs[4] = {vv.x, vv.y, vv.z, vv.w};
    __nv_bfloat16 his[4], los[4];
#pragma unroll
    for (int i = 0; i < 4; i++) {
        int c = tid * 4 + i;
        float val = (vs[i] - mean) * rstd * gamma[c] + beta[c];
        bsplit(val, his[i], los[i]);
    }
    __nv_bfloat162* ph = (__nv_bfloat162*)(g_xlnhi + (size_t)row * Dv + tid * 4);
    __nv_bfloat162* pl = (__nv_bfloat162*)(g_xlnlo + (size_t)row * Dv + tid * 4);
    __nv_bfloat162 a; a.x = his[0]; a.y = his[1]; ph[0] = a;
    a.x = his[2]; a.y = his[3]; ph[1] = a;
    a.x = los[0]; a.y = los[1]; pl[0] = a;
    a.x = los[2]; a.y = los[3]; pl[1] = a;
}

// ---------------- fp32 -> bf16 hi/lo split (float4 vectorized) ----------------
__global__ void split_w(const float* __restrict__ src, __nv_bfloat16* __restrict__ hi,
                        __nv_bfloat16* __restrict__ lo, int n4) {
    int i = blockIdx.x * blockDim.x + threadIdx.x;
    if (i >= n4) return;
    float4 v = ((const float4*)src)[i];
    __nv_bfloat16 h0, l0, h1, l1, h2, l2, h3, l3;
    bsplit(v.x, h0, l0); bsplit(v.y, h1, l1);
    bsplit(v.z, h2, l2); bsplit(v.w, h3, l3);
    __nv_bfloat162 a;
    __nv_bfloat162* ph = (__nv_bfloat162*)(hi + (size_t)i * 4);
    __nv_bfloat162* pl = (__nv_bfloat162*)(lo + (size_t)i * 4);
    a.x = h0; a.y = h1; ph[0] = a;
    a.x = h2; a.y = h3; ph[1] = a;
    a.x = l0; a.y = l1; pl[0] = a;
    a.x = l2; a.y = l3; pl[1] = a;
}

// ---------------- head weight prep (pad to 128 rows, split) ----------------
__global__ void head_prep(const float* __restrict__ Wm, const float* __restrict__ Wl,
                          const float* __restrict__ bm, const float* __restrict__ bl) {
    int i = blockIdx.x * blockDim.x + threadIdx.x;
    if (i < NHEAD * Hv) {
        int r = i / Hv;
        float v = 0.f;
        if (r < Av) v = Wm[i];
        else if (r < 2 * Av) v = Wl[i - Av * Hv];
        __nv_bfloat16 h, l; bsplit(v, h, l);
        g_wheadhi[i] = h; g_wheadlo[i] = l;
    }
    if (i < NHEAD) {
        float b = 0.f;
        if (i < Av) b = bm[i];
        else if (i < 2 * Av) b = bl[i - Av];
        g_bheadp[i] = b;
    }
}

// ---------------- mma.sync bf16-split GEMM ----------------
// C(rows x N) = (Ahi+Alo)(Bhi+Blo)^T (+bias when z==0), dropping Alo*Blo.
// Block 128x128, BK=16, 8 warps (warp tile 64x32), 4-stage cp.async pipeline.
// rowOff: block row offset. PERM=1: A row = time-major->batch-major map.
// UNEV=1: K split into slices 352/336/336 by blockIdx.z (for K=1024, SK=3);
// else K-slice = blockIdx.z*KtileArg. fp32 out to Cp + z*partStride.
// EPI: 0 = fp32 store, 2 = relu + bf16-split store (Chi/Clo).
#define STG_MAT 6144u        // 128 rows * 48B
#define STG_SZ  24576u       // 4 matrices
#define MG_SMEM (4 * 24576)  // 4 stages

template<int EPI, int PERM, int UNEV>
__global__ void __launch_bounds__(256, 1) mgemm(
    int K, int KtileArg, int rowOff,
    const __nv_bfloat16* __restrict__ Ahi, const __nv_bfloat16* __restrict__ Alo,
    const __nv_bfloat16* __restrict__ Bhi, const __nv_bfloat16* __restrict__ Blo,
    const float* __restrict__ bias,
    float* __restrict__ Cp, int ldc, size_t partStride,
    __nv_bfloat16* __restrict__ Chi, __nv_bfloat16* __restrict__ Clo)
{
    extern __shared__ char smem[];
    const uint32_t sb = smem_u32(smem);
    const int tid = threadIdx.x;
    const int wid = tid >> 5, lane = tid & 31;
    const int bm0 = rowOff + blockIdx.y * 128, bn0 = blockIdx.x * 128;
    int kz0, Ktile;
    if (UNEV) {
        kz0 = blockIdx.z * 336 + (blockIdx.z > 0 ? 16 : 0);
        Ktile = (blockIdx.z == 0) ? 352 : 336;
    } else {
        kz0 = blockIdx.z * KtileArg;
        Ktile = KtileArg;
    }
    const int nk = Ktile >> 4;

    // global sources: one 16B chunk per thread per matrix per k-tile
    const int grow = tid >> 1, gch = tid & 1;
    const int growG = bm0 + grow;
    const int arow = PERM ? (((growG & 255) << 7) + (growG >> 8)) : growG;
    const __nv_bfloat16* gp[4];
    gp[0] = Ahi + (size_t)arow * K + kz0 + gch * 8;
    gp[1] = Alo + (size_t)arow * K + kz0 + gch * 8;
    gp[2] = Bhi + (size_t)(bn0 + grow) * K + kz0 + gch * 8;
    gp[3] = Blo + (size_t)(bn0 + grow) * K + kz0 + gch * 8;
    const uint32_t sdst = sb + (uint32_t)grow * 48u + (uint32_t)gch * 16u;

    // prologue: tiles 0,1
#pragma unroll
    for (int it = 0; it < 2; it++) {
        uint32_t s = sdst + (uint32_t)(it & 3) * STG_SZ;
        size_t ko = (size_t)it * 16;
#pragma unroll
        for (int m = 0; m < 4; m++) CP_ASYNC16(s + m * STG_MAT, gp[m] + ko);
        CP_COMMIT();
    }

    // warp tiling
    const int warpM = (wid & 1) * 64;
    const int warpN = (wid >> 1) * 32;
    const uint32_t aoff = (uint32_t)(warpM + (lane & 15)) * 48u + (uint32_t)(lane >> 4) * 16u;
    const uint32_t boff = 2u * STG_MAT +
        (uint32_t)(warpN + ((lane >> 4) << 3) + (lane & 7)) * 48u +
        (uint32_t)((lane >> 3) & 1) * 16u;

    float acc[4][4][4];
#pragma unroll
    for (int i = 0; i < 4; i++)
#pragma unroll
        for (int j = 0; j < 4; j++)
#pragma unroll
            for (int q = 0; q < 4; q++) acc[i][j][q] = 0.f;

    for (int it = 0; it < nk; it++) {
        if (it + 2 < nk) {
            uint32_t s = sdst + (uint32_t)((it + 2) & 3) * STG_SZ;
            size_t ko = (size_t)(it + 2) * 16;
#pragma unroll
            for (int m = 0; m < 4; m++) CP_ASYNC16(s + m * STG_MAT, gp[m] + ko);
        }
        CP_COMMIT();
        CP_WAIT2();
        __syncthreads();

        const uint32_t st = sb + (uint32_t)(it & 3) * STG_SZ;
        uint32_t ah[4][4], al[4][4], bh[2][4], bl[2][4];
#pragma unroll
        for (int mf = 0; mf < 4; mf++) {
            ldsm4(ah[mf], st + aoff + mf * 768u);
            ldsm4(al[mf], st + STG_MAT + aoff + mf * 768u);
        }
#pragma unroll
        for (int p = 0; p < 2; p++) {
            ldsm4(bh[p], st + boff + p * 768u);
            ldsm4(bl[p], st + STG_MAT + boff + p * 768u);
        }
#pragma unroll
        for (int mf = 0; mf < 4; mf++) {
#pragma unroll
            for (int nf = 0; nf < 4; nf++) {
                const int p = nf >> 1, h = (nf & 1) * 2;
                mma_bf16(acc[mf][nf], ah[mf], &bh[p][h]);
                mma_bf16(acc[mf][nf], ah[mf], &bl[p][h]);
                mma_bf16(acc[mf][nf], al[mf], &bh[p][h]);
            }
        }
    }

    // ---- epilogue ----
    const int r = lane >> 2, c2 = (lane & 3) * 2;
#pragma unroll
    for (int mf = 0; mf < 4; mf++) {
#pragma unroll
        for (int nf = 0; nf < 4; nf++) {
            const int row0 = bm0 + warpM + mf * 16 + r;
            const int col  = bn0 + warpN + nf * 8 + c2;
            float b0 = 0.f, b1 = 0.f;
            if (bias != nullptr && blockIdx.z == 0) { b0 = bias[col]; b1 = bias[col + 1]; }
            float v00 = acc[mf][nf][0] + b0, v01 = acc[mf][nf][1] + b1;
            float v10 = acc[mf][nf][2] + b0, v11 = acc[mf][nf][3] + b1;
            if (EPI == 2) {
                v00 = fmaxf(v00, 0.f); v01 = fmaxf(v01, 0.f);
                v10 = fmaxf(v10, 0.f); v11 = fmaxf(v11, 0.f);
                __nv_bfloat16 h0, l0, h1, l1;
                bsplit(v00, h0, l0); bsplit(v01, h1, l1);
                __nv_bfloat162 th; th.x = h0; th.y = h1;
                __nv_bfloat162 tl; tl.x = l0; tl.y = l1;
                *(__nv_bfloat162*)(Chi + (size_t)row0 * ldc + col) = th;
                *(__nv_bfloat162*)(Clo + (size_t)row0 * ldc + col) = tl;
                bsplit(v10, h0, l0); bsplit(v11, h1, l1);
                th.x = h0; th.y = h1; tl.x = l0; tl.y = l1;
                *(__nv_bfloat162*)(Chi + (size_t)(row0 + 8) * ldc + col) = th;
                *(__nv_bfloat162*)(Clo + (size_t)(row0 + 8) * ldc + col) = tl;
            } else {
                float* Co = Cp + blockIdx.z * partStride;
                *(float2*)(Co + (size_t)row0 * ldc + col)       = make_float2(v00, v01);
                *(float2*)(Co + (size_t)(row0 + 8) * ldc + col) = make_float2(v10, v11);
            }
        }
    }
}

// ---------------- GRU gates: fused split-K reduce + elementwise ----------------
// xg / hseq are time-major (row = t*Bv + b)
__global__ void gru_gates(int t, const int* __restrict__ starts,
                          const float* __restrict__ b_hh) {
    int idx = blockIdx.x * blockDim.x + threadIdx.x;
    if (idx >= Bv * Hv) return;
    int b = idx >> 10, j = idx & 1023;
    size_t xrow = ((size_t)t * Bv + b) * G3;
    float xr = g_xg[xrow + j];
    float xz = g_xg[xrow + Hv + j];
    float xn = g_xg[xrow + 2 * Hv + j];
    const size_t PS = (size_t)Bv * G3;
    size_t grow = (size_t)b * G3;
    float hr = b_hh[j], hz = b_hh[Hv + j], hn = b_hh[2 * Hv + j];
#pragma unroll
    for (int z = 0; z < SKv; z++) {
        hr += g_ghp[z * PS + grow + j];
        hz += g_ghp[z * PS + grow + Hv + j];
        hn += g_ghp[z * PS + grow + 2 * Hv + j];
    }
    float st = (float)starts[b * Tv + t];
    float hm = g_h[idx] * (1.0f - st);
    float r = 1.0f / (1.0f + expf(-(xr + hr)));
    float z = 1.0f / (1.0f + expf(-(xz + hz)));
    float n = tanhf(xn + r * hn);
    float hnew = (1.0f - z) * n + z * hm;
    g_h[idx] = hnew;
    __nv_bfloat16 hh, hl;
    bsplit(hnew, hh, hl);
    g_hseqhi[((size_t)t * Bv + b) * Hv + j] = hh;
    g_hseqlo[((size_t)t * Bv + b) * Hv + j] = hl;
    if (t + 1 < Tv) {
        float st2 = (float)starts[b * Tv + t + 1];
        float hm2 = hnew * (1.0f - st2);
        bsplit(hm2, hh, hl);
        g_hmhi[idx] = hh;
        g_hmlo[idx] = hl;
    }
}

// ---------------- head split + clip (per group, time-major source) ----------------
__global__ void head_split(int rowOff, float* __restrict__ out) {
    int idx = blockIdx.x * blockDim.x + threadIdx.x;   // GROWS*64
    if (idx >= GROWS * 64) return;
    int row = rowOff + (idx >> 6), n = idx & 63;       // time-major row
    int t = row >> 8, b = row & 255;
    float v = g_headtmp[(size_t)row * NHEAD + n];
    if (n < Av) {
        out[((size_t)b * Tv + t) * Av + n] = v;
    } else {
        v = fminf(fmaxf(v, -20.0f), 2.0f);
        out[(size_t)BT * Av + ((size_t)b * Tv + t) * Av + (n - Av)] = v;
    }
}

__global__ void init_h(const float* __restrict__ h0, const int* __restrict__ starts) {
    int i = blockIdx.x * blockDim.x + threadIdx.x;
    if (i >= Bv * Hv) return;
    int b = i >> 10;
    float h = h0[i];
    g_h[i] = h;
    float hm = h * (1.0f - (float)starts[b * Tv]);
    __nv_bfloat16 hh, hl; bsplit(hm, hh, hl);
    g_hmhi[i] = hh; g_hmlo[i] = hl;
}
__global__ void emit_h(float* __restrict__ out) {
    int i = blockIdx.x * blockDim.x + threadIdx.x;
    if (i < Bv * Hv) out[i] = g_h[i];
}

extern "C" void kernel_launch(void* const* d_in, const int* in_sizes, int n_in,
                              void* d_out, int out_size) {
    const float* obs    = (const float*)d_in[0];
    const float* h0     = (const float*)d_in[1];
    const int*   starts = (const int*)  d_in[2];
    const float* gamma  = (const float*)d_in[3];
    const float* beta   = (const float*)d_in[4];
    const float* W_fc   = (const float*)d_in[5];
    const float* b_fc   = (const float*)d_in[6];
    const float* W_ih   = (const float*)d_in[7];
    const float* b_ih   = (const float*)d_in[8];
    const float* W_hh   = (const float*)d_in[9];
    const float* b_hh   = (const float*)d_in[10];
    const float* W_out  = (const float*)d_in[11];
    const float* b_out  = (const float*)d_in[12];
    const float* W_mean = (const float*)d_in[13];
    const float* b_mean = (const float*)d_in[14];
    const float* W_ls   = (const float*)d_in[15];
    const float* b_ls   = (const float*)d_in[16];
    float* out = (float*)d_out;

    static cudaStream_t s1 = nullptr, s2 = nullptr;
    static cudaEvent_t evFC, evW, evJoin2;
    static cudaEvent_t evx[NG], evh[NG];
    static bool init_done = false;
    if (!init_done) {
        cudaFuncSetAttribute(mgemm<0, 0, 0>, cudaFuncAttributeMaxDynamicSharedMemorySize, MG_SMEM);
        cudaFuncSetAttribute(mgemm<0, 0, 1>, cudaFuncAttributeMaxDynamicSharedMemorySize, MG_SMEM);
        cudaFuncSetAttribute(mgemm<0, 1, 0>, cudaFuncAttributeMaxDynamicSharedMemorySize, MG_SMEM);
        cudaFuncSetAttribute(mgemm<2, 0, 0>, cudaFuncAttributeMaxDynamicSharedMemorySize, MG_SMEM);
        cudaStreamCreateWithFlags(&s1, cudaStreamNonBlocking);
        cudaStreamCreateWithFlags(&s2, cudaStreamNonBlocking);
        cudaEventCreateWithFlags(&evFC, cudaEventDisableTiming);
        cudaEventCreateWithFlags(&evW, cudaEventDisableTiming);
        cudaEventCreateWithFlags(&evJoin2, cudaEventDisableTiming);
        for (int g = 0; g < NG; g++) {
            cudaEventCreateWithFlags(&evx[g], cudaEventDisableTiming);
            cudaEventCreateWithFlags(&evh[g], cudaEventDisableTiming);
        }
        init_done = true;
    }

    __nv_bfloat16 *xlnhi, *xlnlo, *xhi, *xlo, *hseqhi, *hseqlo, *featshi, *featslo;
    __nv_bfloat16 *hmhi, *hmlo, *wfchi, *wfclo, *wihhi, *wihlo, *whhhi, *whhlo;
    __nv_bfloat16 *wouthi, *woutlo, *wheadhi, *wheadlo;
    float *xg, *ghp, *headtmp, *bheadp;
    cudaGetSymbolAddress((void**)&xlnhi, g_xlnhi);   cudaGetSymbolAddress((void**)&xlnlo, g_xlnlo);
    cudaGetSymbolAddress((void**)&xhi, g_xhi);       cudaGetSymbolAddress((void**)&xlo, g_xlo);
    cudaGetSymbolAddress((void**)&xg, g_xg);
    cudaGetSymbolAddress((void**)&hseqhi, g_hseqhi); cudaGetSymbolAddress((void**)&hseqlo, g_hseqlo);
    cudaGetSymbolAddress((void**)&featshi, g_featshi); cudaGetSymbolAddress((void**)&featslo, g_featslo);
    cudaGetSymbolAddress((void**)&ghp, g_ghp);
    cudaGetSymbolAddress((void**)&hmhi, g_hmhi);     cudaGetSymbolAddress((void**)&hmlo, g_hmlo);
    cudaGetSymbolAddress((void**)&headtmp, g_headtmp);
    cudaGetSymbolAddress((void**)&wfchi, g_wfchi);   cudaGetSymbolAddress((void**)&wfclo, g_wfclo);
    cudaGetSymbolAddress((void**)&wihhi, g_wihhi);   cudaGetSymbolAddress((void**)&wihlo, g_wihlo);
    cudaGetSymbolAddress((void**)&whhhi, g_whhhi);   cudaGetSymbolAddress((void**)&whhlo, g_whhlo);
    cudaGetSymbolAddress((void**)&wouthi, g_wouthi); cudaGetSymbolAddress((void**)&woutlo, g_woutlo);
    cudaGetSymbolAddress((void**)&wheadhi, g_wheadhi); cudaGetSymbolAddress((void**)&wheadlo, g_wheadlo);
    cudaGetSymbolAddress((void**)&bheadp, g_bheadp);

    const size_t PS = (size_t)Bv * G3;

    // ---- stream 0, deterministic prefix (launches 1..6; 6th = FC mgemm for ncu) ----
    split_w<<<(FCv * Dv / 4 + 255) / 256, 256>>>(W_fc, wfchi, wfclo, FCv * Dv / 4);     // 1
    split_w<<<(G3 * FCv / 4 + 255) / 256, 256>>>(W_ih, wihhi, wihlo, G3 * FCv / 4);     // 2
    split_w<<<(G3 * Hv / 4 + 255) / 256, 256>>>(W_hh, whhhi, whhlo, G3 * Hv / 4);       // 3
    split_w<<<(Hv * Hv / 4 + 255) / 256, 256>>>(W_out, wouthi, woutlo, Hv * Hv / 4);    // 4
    ln_kernel<<<BT, 128>>>(obs, gamma, beta);                                            // 5
    mgemm<2, 0, 0><<<dim3(FCv / 128, BT / 128, 1), 256, MG_SMEM>>>(                      // 6
        Dv, Dv, 0, xlnhi, xlnlo, wfchi, wfclo, b_fc, nullptr, FCv, 0, xhi, xlo);
    cudaEventRecord(evFC, 0);
    head_prep<<<(NHEAD * Hv + 255) / 256, 256>>>(W_mean, W_ls, b_mean, b_ls);
    cudaEventRecord(evW, 0);
    init_h<<<(Bv * Hv + 255) / 256, 256>>>(h0, starts);

    // ---- s1: xg production in NG chunks (time-major out, PERM on A rows) ----
    cudaStreamWaitEvent(s1, evFC, 0);
    for (int g = 0; g < NG; g++) {
        mgemm<0, 1, 0><<<dim3(G3 / 128, GROWS / 128, 1), 256, MG_SMEM, s1>>>(
            FCv, FCv, g * GROWS, xhi, xlo, wihhi, wihlo, b_ih, xg, G3, 0, nullptr, nullptr);
        cudaEventRecord(evx[g], s1);
    }

    // ---- s0: scan ----
    for (int g = 0; g < NG; g++) {
        cudaStreamWaitEvent(0, evx[g], 0);
        for (int tt = 0; tt < GRP; tt++) {
            int t = g * GRP + tt;
            mgemm<0, 0, 1><<<dim3(G3 / 128, Bv / 128, SKv), 256, MG_SMEM>>>(
                Hv, 0, 0, hmhi, hmlo, whhhi, whhlo, nullptr, ghp, G3, PS, nullptr, nullptr);
            gru_gates<<<(Bv * Hv + 255) / 256, 256>>>(t, starts, b_hh);
        }
        cudaEventRecord(evh[g], 0);
    }
    emit_h<<<(Bv * Hv + 255) / 256, 256>>>(out + 2 * (size_t)BT * Av);

    // ---- s2: out-projection + heads per group ----
    cudaStreamWaitEvent(s2, evW, 0);
    for (int g = 0; g < NG; g++) {
        cudaStreamWaitEvent(s2, evh[g], 0);
        mgemm<2, 0, 0><<<dim3(Hv / 128, GROWS / 128, 1), 256, MG_SMEM, s2>>>(
            Hv, Hv, g * GROWS, hseqhi, hseqlo, wouthi, woutlo, b_out, nullptr, Hv, 0, featshi, featslo);
        mgemm<0, 0, 0><<<dim3(1, GROWS / 128, 1), 256, MG_SMEM, s2>>>(
            Hv, Hv, g * GROWS, featshi, featslo, wheadhi, wheadlo, bheadp, headtmp, NHEAD, 0, nullptr, nullptr);
        head_split<<<(GROWS * 64 + 255) / 256, 256, 0, s2>>>(g * GROWS, out);
    }
    cudaEventRecord(evJoin2, s2);

    // ---- join ----
    cudaStreamWaitEvent(0, evJoin2, 0);
}